// round 1
// baseline (speedup 1.0000x reference)
#include <cuda_runtime.h>
#include <cuda_bf16.h>
#include <math.h>

#define N_TOK 6144
#define D_MODEL 256
#define N_HEADS 4
#define D_HEAD 64
#define D_FF 1024
#define LN_EPS 1e-5f

// ---------------- scratch (static device globals; no allocation) ----------------
__device__ float g_qkv [N_TOK * 3 * D_MODEL];   // 18.9 MB
__device__ float g_attn[N_TOK * D_MODEL];       // 6.3 MB
__device__ float g_x1  [N_TOK * D_MODEL];       // 6.3 MB
__device__ float g_ffh [N_TOK * D_FF];          // 25.2 MB
__device__ float g_tmp [N_TOK * D_MODEL];       // 6.3 MB

// ---------------- tiled SGEMM: C[M,N] = A[M,K] @ B[K,N] + bias (+GELU) ----------
// 128x128 tile, BK=16, 256 threads, 8x8 per thread. M,N,K all divisible.
template<int K, int N, bool DOGELU>
__global__ __launch_bounds__(256) void sgemm_bias(
    const float* __restrict__ A, const float* __restrict__ B,
    const float* __restrict__ bias, float* __restrict__ C)
{
    constexpr int LDSH = 132;                 // pad: 16B-aligned rows, conflict-light
    __shared__ float As[16][LDSH];
    __shared__ float Bs[16][LDSH];

    const int tid  = threadIdx.x;
    const int row0 = blockIdx.y * 128;
    const int col0 = blockIdx.x * 128;
    const int tx = tid & 15, ty = tid >> 4;

    float acc[8][8];
#pragma unroll
    for (int i = 0; i < 8; i++)
#pragma unroll
        for (int j = 0; j < 8; j++) acc[i][j] = 0.f;

    for (int kt = 0; kt < K; kt += 16) {
#pragma unroll
        for (int l = 0; l < 2; l++) {
            int idx4 = tid * 2 + l;
            // A tile: 128 rows x 16 cols -> store transposed As[k][m]
            int ar = idx4 >> 2, ac = (idx4 & 3) * 4;
            float4 va = *reinterpret_cast<const float4*>(A + (size_t)(row0 + ar) * K + kt + ac);
            As[ac + 0][ar] = va.x;
            As[ac + 1][ar] = va.y;
            As[ac + 2][ar] = va.z;
            As[ac + 3][ar] = va.w;
            // B tile: 16 rows x 128 cols, direct
            int br = idx4 >> 5, bc = (idx4 & 31) * 4;
            *reinterpret_cast<float4*>(&Bs[br][bc]) =
                *reinterpret_cast<const float4*>(B + (size_t)(kt + br) * N + col0 + bc);
        }
        __syncthreads();
#pragma unroll
        for (int kk = 0; kk < 16; kk++) {
            float a[8], bf[8];
            *(float4*)(a)      = *(const float4*)&As[kk][ty * 8];
            *(float4*)(a + 4)  = *(const float4*)&As[kk][ty * 8 + 4];
            *(float4*)(bf)     = *(const float4*)&Bs[kk][tx * 8];
            *(float4*)(bf + 4) = *(const float4*)&Bs[kk][tx * 8 + 4];
#pragma unroll
            for (int i = 0; i < 8; i++)
#pragma unroll
                for (int j = 0; j < 8; j++) acc[i][j] = fmaf(a[i], bf[j], acc[i][j]);
        }
        __syncthreads();
    }

#pragma unroll
    for (int i = 0; i < 8; i++) {
        int r = row0 + ty * 8 + i;
#pragma unroll
        for (int jj = 0; jj < 2; jj++) {
            int c = col0 + tx * 8 + jj * 4;
            float4 bv = *reinterpret_cast<const float4*>(bias + c);
            float4 o;
            o.x = acc[i][jj * 4 + 0] + bv.x;
            o.y = acc[i][jj * 4 + 1] + bv.y;
            o.z = acc[i][jj * 4 + 2] + bv.z;
            o.w = acc[i][jj * 4 + 3] + bv.w;
            if (DOGELU) {
                o.x = 0.5f * o.x * (1.f + erff(o.x * 0.70710678118654752f));
                o.y = 0.5f * o.y * (1.f + erff(o.y * 0.70710678118654752f));
                o.z = 0.5f * o.z * (1.f + erff(o.z * 0.70710678118654752f));
                o.w = 0.5f * o.w * (1.f + erff(o.w * 0.70710678118654752f));
            }
            *reinterpret_cast<float4*>(C + (size_t)r * N + c) = o;
        }
    }
}

// ---------------- segment attention: one warp per (token, head) -----------------
// doc index sorted -> segment via binary search; online softmax over segment.
__global__ __launch_bounds__(256) void attn_kernel(
    const float* __restrict__ qkv, const int* __restrict__ doc,
    float* __restrict__ out)
{
    int wg = (blockIdx.x * 256 + threadIdx.x) >> 5;
    int lane = threadIdx.x & 31;
    if (wg >= N_TOK * N_HEADS) return;
    int i = wg >> 2;
    int h = wg & 3;

    int my = doc[i];
    // lower_bound(my)
    int lo = 0, hi = N_TOK;
    while (lo < hi) { int mid = (lo + hi) >> 1; if (doc[mid] < my) lo = mid + 1; else hi = mid; }
    int s = lo;
    // upper_bound(my)
    lo = i; hi = N_TOK;  // my segment contains i, so upper bound >= i
    while (lo < hi) { int mid = (lo + hi) >> 1; if (doc[mid] <= my) lo = mid + 1; else hi = mid; }
    int e = lo;

    const float* q = qkv + (size_t)i * (3 * D_MODEL) + h * D_HEAD;
    float q0 = q[lane], q1 = q[lane + 32];
    const float* kbase = qkv + D_MODEL + h * D_HEAD;
    const float* vbase = qkv + 2 * D_MODEL + h * D_HEAD;

    float m = -3.4e38f, sum = 0.f, o0 = 0.f, o1 = 0.f;
    for (int j = s; j < e; j++) {
        const float* kr = kbase + (size_t)j * (3 * D_MODEL);
        float d = q0 * kr[lane] + q1 * kr[lane + 32];
#pragma unroll
        for (int off = 16; off; off >>= 1) d += __shfl_xor_sync(0xffffffffu, d, off);
        float sc = d * 0.125f;  // 1/sqrt(64)
        float mn = fmaxf(m, sc);
        float corr = __expf(m - mn);   // first iter: exp(-inf)=0, state is 0 anyway
        float p = __expf(sc - mn);
        const float* vr = vbase + (size_t)j * (3 * D_MODEL);
        sum = sum * corr + p;
        o0 = o0 * corr + p * vr[lane];
        o1 = o1 * corr + p * vr[lane + 32];
        m = mn;
    }
    float inv = 1.f / sum;
    out[(size_t)i * D_MODEL + h * D_HEAD + lane]      = o0 * inv;
    out[(size_t)i * D_MODEL + h * D_HEAD + lane + 32] = o1 * inv;
}

// ---------------- residual + layernorm: one block (256 thr) per row -------------
__global__ __launch_bounds__(256) void ln_kernel(
    const float* __restrict__ y, const float* __restrict__ res,
    const float* __restrict__ g, const float* __restrict__ b,
    float* __restrict__ out)
{
    int row = blockIdx.x, j = threadIdx.x;
    size_t off = (size_t)row * D_MODEL + j;
    float v = y[off] + res[off];
    float s = v, sq = v * v;
#pragma unroll
    for (int o = 16; o; o >>= 1) {
        s  += __shfl_xor_sync(0xffffffffu, s, o);
        sq += __shfl_xor_sync(0xffffffffu, sq, o);
    }
    __shared__ float ss[8], sqs[8];
    if ((j & 31) == 0) { ss[j >> 5] = s; sqs[j >> 5] = sq; }
    __syncthreads();
    float ts = 0.f, tq = 0.f;
#pragma unroll
    for (int w = 0; w < 8; w++) { ts += ss[w]; tq += sqs[w]; }
    float mu  = ts * (1.f / D_MODEL);
    float var = tq * (1.f / D_MODEL) - mu * mu;
    out[off] = (v - mu) * rsqrtf(var + LN_EPS) * g[j] + b[j];
}

// ---------------- launch ---------------------------------------------------------
extern "C" void kernel_launch(void* const* d_in, const int* in_sizes, int n_in,
                              void* d_out, int out_size)
{
    const float* x      = (const float*)d_in[0];
    const int*   doc    = (const int*)  d_in[1];
    const float* qkv_w  = (const float*)d_in[2];
    const float* qkv_b  = (const float*)d_in[3];
    const float* out_w  = (const float*)d_in[4];
    const float* out_b  = (const float*)d_in[5];
    const float* ff_w1  = (const float*)d_in[6];
    const float* ff_b1  = (const float*)d_in[7];
    const float* ff_w2  = (const float*)d_in[8];
    const float* ff_b2  = (const float*)d_in[9];
    const float* ln1_g  = (const float*)d_in[10];
    const float* ln1_b  = (const float*)d_in[11];
    const float* ln2_g  = (const float*)d_in[12];
    const float* ln2_b  = (const float*)d_in[13];
    float* out = (float*)d_out;

    float *qkv, *attn, *x1, *ffh, *tmp;
    cudaGetSymbolAddress((void**)&qkv,  g_qkv);
    cudaGetSymbolAddress((void**)&attn, g_attn);
    cudaGetSymbolAddress((void**)&x1,   g_x1);
    cudaGetSymbolAddress((void**)&ffh,  g_ffh);
    cudaGetSymbolAddress((void**)&tmp,  g_tmp);

    const int MT = N_TOK / 128;  // 48 row tiles

    // 1. QKV = x @ qkv_w + qkv_b
    sgemm_bias<D_MODEL, 3 * D_MODEL, false><<<dim3(3 * D_MODEL / 128, MT), 256>>>(x, qkv_w, qkv_b, qkv);
    // 2. segment attention
    attn_kernel<<<(N_TOK * N_HEADS) / 8, 256>>>(qkv, doc, attn);
    // 3. proj = attn @ out_w + out_b
    sgemm_bias<D_MODEL, D_MODEL, false><<<dim3(D_MODEL / 128, MT), 256>>>(attn, out_w, out_b, tmp);
    // 4. x1 = LN(x + proj)
    ln_kernel<<<N_TOK, 256>>>(tmp, x, ln1_g, ln1_b, x1);
    // 5. h = gelu(x1 @ ff_w1 + ff_b1)
    sgemm_bias<D_MODEL, D_FF, true><<<dim3(D_FF / 128, MT), 256>>>(x1, ff_w1, ff_b1, ffh);
    // 6. f2 = h @ ff_w2 + ff_b2
    sgemm_bias<D_FF, D_MODEL, false><<<dim3(D_MODEL / 128, MT), 256>>>(ffh, ff_w2, ff_b2, tmp);
    // 7. out = LN(x1 + f2)
    ln_kernel<<<N_TOK, 256>>>(tmp, x1, ln2_g, ln2_b, out);
}

// round 4
// speedup vs baseline: 2.5184x; 2.5184x over previous
#include <cuda_runtime.h>
#include <cuda_bf16.h>
#include <math.h>

#define N_TOK 6144
#define D_MODEL 256
#define N_HEADS 4
#define D_HEAD 64
#define D_FF 1024
#define LN_EPS 1e-5f

// ---------------- scratch (static device globals; no allocation) ----------------
__device__ float g_qkv [N_TOK * 3 * D_MODEL];
__device__ float g_attn[N_TOK * D_MODEL];
__device__ float g_x1  [N_TOK * D_MODEL];
__device__ float g_ffh [N_TOK * D_FF];
__device__ float g_tmp [N_TOK * D_MODEL];

// ---------------- helpers --------------------------------------------------------
__device__ __forceinline__ unsigned f2tf32(float f) {
    unsigned r;
    asm("cvt.rna.tf32.f32 %0, %1;" : "=r"(r) : "f"(f));
    return r;
}
__device__ __forceinline__ void cp16(void* smem_dst, const void* gsrc) {
    unsigned d = (unsigned)__cvta_generic_to_shared(smem_dst);
    asm volatile("cp.async.cg.shared.global [%0], [%1], 16;\n" :: "r"(d), "l"(gsrc));
}
__device__ __forceinline__ void cp_commit() { asm volatile("cp.async.commit_group;\n"); }
template<int NLEFT>
__device__ __forceinline__ void cp_wait() { asm volatile("cp.async.wait_group %0;\n" :: "n"(NLEFT)); }

__device__ __forceinline__ void mma_tf32(
    float& c0, float& c1, float& c2, float& c3,
    unsigned a0, unsigned a1, unsigned a2, unsigned a3,
    unsigned b0, unsigned b1)
{
    asm volatile(
        "mma.sync.aligned.m16n8k8.row.col.f32.tf32.tf32.f32 "
        "{%0,%1,%2,%3}, {%4,%5,%6,%7}, {%8,%9}, {%0,%1,%2,%3};\n"
        : "+f"(c0), "+f"(c1), "+f"(c2), "+f"(c3)
        : "r"(a0), "r"(a1), "r"(a2), "r"(a3), "r"(b0), "r"(b1));
}

// ---------------- tf32 tensor-core GEMM: C = A[M,K]@B[K,N] + bias (+GELU) --------
// 128x128 block tile, BK=16, double-buffered cp.async. 8 warps (2x4), warp 64x32.
#define BK 16
#define A_STR 20    // padded stride (words): conflict-free for frag pattern
#define B_STR 136

template<int K, int N, bool DOGELU>
__global__ __launch_bounds__(256, 2) void gemm_tf32(
    const float* __restrict__ A, const float* __restrict__ B,
    const float* __restrict__ bias, float* __restrict__ C)
{
    __shared__ float As[2][128][A_STR];
    __shared__ float Bs[2][BK][B_STR];

    const int tid  = threadIdx.x;
    const int row0 = blockIdx.y * 128;
    const int col0 = blockIdx.x * 128;
    const int w    = tid >> 5;
    const int lane = tid & 31;
    const int wm = w & 1;          // 0..1  -> M offset 64*wm
    const int wn = w >> 1;         // 0..3  -> N offset 32*wn
    const int g  = lane >> 2;      // group 0..7
    const int t4 = lane & 3;       // 0..3

    float acc[4][4][4];
#pragma unroll
    for (int mi = 0; mi < 4; mi++)
#pragma unroll
        for (int ni = 0; ni < 4; ni++)
#pragma unroll
            for (int r = 0; r < 4; r++) acc[mi][ni][r] = 0.f;

    // staging indices (each thread does 2 A float4s + 2 B float4s per ktile)
    const int ar0 = tid >> 2,        ac0 = (tid & 3) * 4;          // A: 512 float4, t and t+256
    const int ar1 = (tid + 256) >> 2, ac1 = ((tid + 256) & 3) * 4;
    const int br0 = tid >> 5,        bc0 = (tid & 31) * 4;
    const int br1 = (tid + 256) >> 5, bc1 = ((tid + 256) & 31) * 4;

    auto stage = [&](int kt, int buf) {
        cp16(&As[buf][ar0][ac0], A + (size_t)(row0 + ar0) * K + kt + ac0);
        cp16(&As[buf][ar1][ac1], A + (size_t)(row0 + ar1) * K + kt + ac1);
        cp16(&Bs[buf][br0][bc0], B + (size_t)(kt + br0) * N + col0 + bc0);
        cp16(&Bs[buf][br1][bc1], B + (size_t)(kt + br1) * N + col0 + bc1);
        cp_commit();
    };

    constexpr int T = K / BK;
    stage(0, 0);

    for (int t = 0; t < T; t++) {
        int buf = t & 1;
        if (t + 1 < T) {
            stage((t + 1) * BK, 1 - buf);
            cp_wait<1>();
        } else {
            cp_wait<0>();
        }
        __syncthreads();

#pragma unroll
        for (int ks = 0; ks < 2; ks++) {
            const int k0 = ks * 8;
            unsigned af[4][4], bf[4][2];
#pragma unroll
            for (int mi = 0; mi < 4; mi++) {
                const int rb = wm * 64 + mi * 16;
                af[mi][0] = f2tf32(As[buf][rb + g    ][k0 + t4    ]);
                af[mi][1] = f2tf32(As[buf][rb + g + 8][k0 + t4    ]);
                af[mi][2] = f2tf32(As[buf][rb + g    ][k0 + t4 + 4]);
                af[mi][3] = f2tf32(As[buf][rb + g + 8][k0 + t4 + 4]);
            }
#pragma unroll
            for (int ni = 0; ni < 4; ni++) {
                const int nb = wn * 32 + ni * 8;
                bf[ni][0] = f2tf32(Bs[buf][k0 + t4    ][nb + g]);
                bf[ni][1] = f2tf32(Bs[buf][k0 + t4 + 4][nb + g]);
            }
#pragma unroll
            for (int mi = 0; mi < 4; mi++)
#pragma unroll
                for (int ni = 0; ni < 4; ni++)
                    mma_tf32(acc[mi][ni][0], acc[mi][ni][1], acc[mi][ni][2], acc[mi][ni][3],
                             af[mi][0], af[mi][1], af[mi][2], af[mi][3],
                             bf[ni][0], bf[ni][1]);
        }
        __syncthreads();
    }

    // epilogue: bias (+gelu), float2 stores
#pragma unroll
    for (int mi = 0; mi < 4; mi++) {
        const int r0g = row0 + wm * 64 + mi * 16 + g;
#pragma unroll
        for (int ni = 0; ni < 4; ni++) {
            const int c = col0 + wn * 32 + ni * 8 + t4 * 2;
            const float bx = bias[c], by = bias[c + 1];
            float v0 = acc[mi][ni][0] + bx, v1 = acc[mi][ni][1] + by;
            float v2 = acc[mi][ni][2] + bx, v3 = acc[mi][ni][3] + by;
            if (DOGELU) {
                v0 = 0.5f * v0 * (1.f + erff(v0 * 0.70710678118654752f));
                v1 = 0.5f * v1 * (1.f + erff(v1 * 0.70710678118654752f));
                v2 = 0.5f * v2 * (1.f + erff(v2 * 0.70710678118654752f));
                v3 = 0.5f * v3 * (1.f + erff(v3 * 0.70710678118654752f));
            }
            *reinterpret_cast<float2*>(C + (size_t)r0g * N + c)       = make_float2(v0, v1);
            *reinterpret_cast<float2*>(C + (size_t)(r0g + 8) * N + c) = make_float2(v2, v3);
        }
    }
}

// ---------------- segment attention: one warp per (token, head) -----------------
__global__ __launch_bounds__(256) void attn_kernel(
    const float* __restrict__ qkv, const int* __restrict__ doc,
    float* __restrict__ out)
{
    int wg = (blockIdx.x * 256 + threadIdx.x) >> 5;
    int lane = threadIdx.x & 31;
    if (wg >= N_TOK * N_HEADS) return;
    int i = wg >> 2;
    int h = wg & 3;

    int my = doc[i];
    int lo = 0, hi = N_TOK;
    while (lo < hi) { int mid = (lo + hi) >> 1; if (doc[mid] < my) lo = mid + 1; else hi = mid; }
    int s = lo;
    lo = i; hi = N_TOK;
    while (lo < hi) { int mid = (lo + hi) >> 1; if (doc[mid] <= my) lo = mid + 1; else hi = mid; }
    int e = lo;

    const float* q = qkv + (size_t)i * (3 * D_MODEL) + h * D_HEAD;
    float q0 = q[lane], q1 = q[lane + 32];
    const float* kbase = qkv + D_MODEL + h * D_HEAD;
    const float* vbase = qkv + 2 * D_MODEL + h * D_HEAD;

    float m = -3.4e38f, sum = 0.f, o0 = 0.f, o1 = 0.f;
    for (int j = s; j < e; j++) {
        const float* kr = kbase + (size_t)j * (3 * D_MODEL);
        float d = q0 * kr[lane] + q1 * kr[lane + 32];
#pragma unroll
        for (int off = 16; off; off >>= 1) d += __shfl_xor_sync(0xffffffffu, d, off);
        float sc = d * 0.125f;
        float mn = fmaxf(m, sc);
        float corr = __expf(m - mn);
        float p = __expf(sc - mn);
        const float* vr = vbase + (size_t)j * (3 * D_MODEL);
        sum = sum * corr + p;
        o0 = o0 * corr + p * vr[lane];
        o1 = o1 * corr + p * vr[lane + 32];
        m = mn;
    }
    float inv = 1.f / sum;
    out[(size_t)i * D_MODEL + h * D_HEAD + lane]      = o0 * inv;
    out[(size_t)i * D_MODEL + h * D_HEAD + lane + 32] = o1 * inv;
}

// ---------------- residual + layernorm: one warp per row ------------------------
__global__ __launch_bounds__(256) void ln_kernel(
    const float* __restrict__ y, const float* __restrict__ res,
    const float* __restrict__ gw, const float* __restrict__ bw,
    float* __restrict__ out)
{
    int row = blockIdx.x * 8 + (threadIdx.x >> 5);
    int lane = threadIdx.x & 31;
    size_t base = (size_t)row * D_MODEL;

    float4 a0 = *reinterpret_cast<const float4*>(y + base + lane * 4);
    float4 r0 = *reinterpret_cast<const float4*>(res + base + lane * 4);
    float4 a1 = *reinterpret_cast<const float4*>(y + base + 128 + lane * 4);
    float4 r1 = *reinterpret_cast<const float4*>(res + base + 128 + lane * 4);
    a0.x += r0.x; a0.y += r0.y; a0.z += r0.z; a0.w += r0.w;
    a1.x += r1.x; a1.y += r1.y; a1.z += r1.z; a1.w += r1.w;

    float s  = a0.x + a0.y + a0.z + a0.w + a1.x + a1.y + a1.z + a1.w;
    float sq = a0.x*a0.x + a0.y*a0.y + a0.z*a0.z + a0.w*a0.w
             + a1.x*a1.x + a1.y*a1.y + a1.z*a1.z + a1.w*a1.w;
#pragma unroll
    for (int o = 16; o; o >>= 1) {
        s  += __shfl_xor_sync(0xffffffffu, s, o);
        sq += __shfl_xor_sync(0xffffffffu, sq, o);
    }
    float mu  = s * (1.f / D_MODEL);
    float var = sq * (1.f / D_MODEL) - mu * mu;
    float inv = rsqrtf(var + LN_EPS);

    float4 g0 = *reinterpret_cast<const float4*>(gw + lane * 4);
    float4 b0 = *reinterpret_cast<const float4*>(bw + lane * 4);
    float4 g1 = *reinterpret_cast<const float4*>(gw + 128 + lane * 4);
    float4 b1 = *reinterpret_cast<const float4*>(bw + 128 + lane * 4);
    float4 o0, o1;
    o0.x = (a0.x - mu) * inv * g0.x + b0.x;
    o0.y = (a0.y - mu) * inv * g0.y + b0.y;
    o0.z = (a0.z - mu) * inv * g0.z + b0.z;
    o0.w = (a0.w - mu) * inv * g0.w + b0.w;
    o1.x = (a1.x - mu) * inv * g1.x + b1.x;
    o1.y = (a1.y - mu) * inv * g1.y + b1.y;
    o1.z = (a1.z - mu) * inv * g1.z + b1.z;
    o1.w = (a1.w - mu) * inv * g1.w + b1.w;
    *reinterpret_cast<float4*>(out + base + lane * 4)       = o0;
    *reinterpret_cast<float4*>(out + base + 128 + lane * 4) = o1;
}

// ---------------- launch ---------------------------------------------------------
extern "C" void kernel_launch(void* const* d_in, const int* in_sizes, int n_in,
                              void* d_out, int out_size)
{
    const float* x      = (const float*)d_in[0];
    const int*   doc    = (const int*)  d_in[1];
    const float* qkv_w  = (const float*)d_in[2];
    const float* qkv_b  = (const float*)d_in[3];
    const float* out_w  = (const float*)d_in[4];
    const float* out_b  = (const float*)d_in[5];
    const float* ff_w1  = (const float*)d_in[6];
    const float* ff_b1  = (const float*)d_in[7];
    const float* ff_w2  = (const float*)d_in[8];
    const float* ff_b2  = (const float*)d_in[9];
    const float* ln1_g  = (const float*)d_in[10];
    const float* ln1_b  = (const float*)d_in[11];
    const float* ln2_g  = (const float*)d_in[12];
    const float* ln2_b  = (const float*)d_in[13];
    float* out = (float*)d_out;

    float *qkv, *attn, *x1, *ffh, *tmp;
    cudaGetSymbolAddress((void**)&qkv,  g_qkv);
    cudaGetSymbolAddress((void**)&attn, g_attn);
    cudaGetSymbolAddress((void**)&x1,   g_x1);
    cudaGetSymbolAddress((void**)&ffh,  g_ffh);
    cudaGetSymbolAddress((void**)&tmp,  g_tmp);

    const int MT = N_TOK / 128;  // 48 row tiles

    gemm_tf32<D_MODEL, 3 * D_MODEL, false><<<dim3(3 * D_MODEL / 128, MT), 256>>>(x, qkv_w, qkv_b, qkv);
    attn_kernel<<<(N_TOK * N_HEADS) / 8, 256>>>(qkv, doc, attn);
    gemm_tf32<D_MODEL, D_MODEL, false><<<dim3(D_MODEL / 128, MT), 256>>>(attn, out_w, out_b, tmp);
    ln_kernel<<<N_TOK / 8, 256>>>(tmp, x, ln1_g, ln1_b, x1);
    gemm_tf32<D_MODEL, D_FF, true><<<dim3(D_FF / 128, MT), 256>>>(x1, ff_w1, ff_b1, ffh);
    gemm_tf32<D_FF, D_MODEL, false><<<dim3(D_MODEL / 128, MT), 256>>>(ffh, ff_w2, ff_b2, tmp);
    ln_kernel<<<N_TOK / 8, 256>>>(tmp, x1, ln2_g, ln2_b, out);
}

// round 5
// speedup vs baseline: 3.6583x; 1.4526x over previous
#include <cuda_runtime.h>
#include <cuda_bf16.h>
#include <math.h>

#define N_TOK 6144
#define D_MODEL 256
#define N_HEADS 4
#define D_HEAD 64
#define D_FF 1024
#define LN_EPS 1e-5f

// ---------------- scratch (static device globals; no allocation) ----------------
__device__ float g_qkv [N_TOK * 3 * D_MODEL];           // fp32 (attention reads)
__device__ float g_x1  [N_TOK * D_MODEL];
__device__ float g_tmp [N_TOK * D_MODEL];
__device__ __nv_bfloat16 g_xb   [N_TOK * D_MODEL];      // bf16 activations/weights
__device__ __nv_bfloat16 g_attnb[N_TOK * D_MODEL];
__device__ __nv_bfloat16 g_x1b  [N_TOK * D_MODEL];
__device__ __nv_bfloat16 g_ffhb [N_TOK * D_FF];
__device__ __nv_bfloat16 g_wq   [D_MODEL * 3 * D_MODEL];
__device__ __nv_bfloat16 g_wo   [D_MODEL * D_MODEL];
__device__ __nv_bfloat16 g_w1   [D_MODEL * D_FF];
__device__ __nv_bfloat16 g_w2   [D_FF * D_MODEL];

// ---------------- helpers --------------------------------------------------------
__device__ __forceinline__ void cp16(void* smem_dst, const void* gsrc) {
    unsigned d = (unsigned)__cvta_generic_to_shared(smem_dst);
    asm volatile("cp.async.cg.shared.global [%0], [%1], 16;\n" :: "r"(d), "l"(gsrc));
}
__device__ __forceinline__ void cp_commit() { asm volatile("cp.async.commit_group;\n"); }
__device__ __forceinline__ void cp_wait0()  { asm volatile("cp.async.wait_group 0;\n"); }

__device__ __forceinline__ void ldsm_x4(unsigned& r0, unsigned& r1, unsigned& r2, unsigned& r3,
                                        const void* p) {
    unsigned a = (unsigned)__cvta_generic_to_shared(p);
    asm volatile("ldmatrix.sync.aligned.m8n8.x4.shared.b16 {%0,%1,%2,%3}, [%4];"
                 : "=r"(r0), "=r"(r1), "=r"(r2), "=r"(r3) : "r"(a));
}
__device__ __forceinline__ void ldsm_x2t(unsigned& r0, unsigned& r1, const void* p) {
    unsigned a = (unsigned)__cvta_generic_to_shared(p);
    asm volatile("ldmatrix.sync.aligned.m8n8.x2.trans.shared.b16 {%0,%1}, [%2];"
                 : "=r"(r0), "=r"(r1) : "r"(a));
}
__device__ __forceinline__ void mma_bf16(
    float& c0, float& c1, float& c2, float& c3,
    unsigned a0, unsigned a1, unsigned a2, unsigned a3,
    unsigned b0, unsigned b1)
{
    asm volatile(
        "mma.sync.aligned.m16n8k16.row.col.f32.bf16.bf16.f32 "
        "{%0,%1,%2,%3}, {%4,%5,%6,%7}, {%8,%9}, {%0,%1,%2,%3};\n"
        : "+f"(c0), "+f"(c1), "+f"(c2), "+f"(c3)
        : "r"(a0), "r"(a1), "r"(a2), "r"(a3), "r"(b0), "r"(b1));
}

// ---------------- bf16 tensor-core GEMM: C = A[M,K]@B[K,N] + bias (+GELU) --------
// 128x128 block tile, BK=32 (bf16), single-sync double buffer via cp.async.
// 8 warps (2x4), warp tile 64x32, m16n8k16 fragments via ldmatrix.
#define BK 32
#define A_STR 40    // bf16 words; 80B row stride (5x16B) -> conflict-free ldmatrix
#define B_STR 136   // 272B row stride (17x16B)

template<int K, int N, bool DOGELU, bool OUTBF16>
__global__ __launch_bounds__(256, 2) void gemm_bf16_k(
    const __nv_bfloat16* __restrict__ A, const __nv_bfloat16* __restrict__ B,
    const float* __restrict__ bias, void* __restrict__ Cv)
{
    __shared__ __nv_bfloat16 As[2][128][A_STR];
    __shared__ __nv_bfloat16 Bs[2][BK][B_STR];

    const int tid  = threadIdx.x;
    const int row0 = blockIdx.y * 128;
    const int col0 = blockIdx.x * 128;
    const int w    = tid >> 5;
    const int lane = tid & 31;
    const int wm = w & 1;
    const int wn = w >> 1;
    const int g  = lane >> 2;
    const int t4 = lane & 3;

    float acc[4][4][4];
#pragma unroll
    for (int mi = 0; mi < 4; mi++)
#pragma unroll
        for (int ni = 0; ni < 4; ni++)
#pragma unroll
            for (int r = 0; r < 4; r++) acc[mi][ni][r] = 0.f;

    // staging: A 128x32/8 = 512 chunks, B 32x128/8 = 512 chunks; 2 each per thread
    const int ar0 = tid >> 2,         ac0 = (tid & 3) * 8;
    const int ar1 = (tid + 256) >> 2, ac1 = ((tid + 256) & 3) * 8;
    const int br0 = tid >> 4,         bc0 = (tid & 15) * 8;
    const int br1 = (tid + 256) >> 4, bc1 = ((tid + 256) & 15) * 8;

    auto stage = [&](int kt, int buf) {
        cp16(&As[buf][ar0][ac0], A + (size_t)(row0 + ar0) * K + kt + ac0);
        cp16(&As[buf][ar1][ac1], A + (size_t)(row0 + ar1) * K + kt + ac1);
        cp16(&Bs[buf][br0][bc0], B + (size_t)(kt + br0) * N + col0 + bc0);
        cp16(&Bs[buf][br1][bc1], B + (size_t)(kt + br1) * N + col0 + bc1);
        cp_commit();
    };

    constexpr int T = K / BK;
    stage(0, 0);

    // ldmatrix lane addressing
    const int a_row = lane & 15;              // + rb
    const int a_col = ((lane >> 4) << 3);     // + ks*16
    const int b_row = lane & 15;              // + ks*16

    for (int t = 0; t < T; t++) {
        cp_wait0();
        __syncthreads();
        if (t + 1 < T) stage((t + 1) * BK, (t + 1) & 1);
        const int buf = t & 1;

#pragma unroll
        for (int ks = 0; ks < 2; ks++) {
            const int kc = ks * 16;
            unsigned af[4][4], bf[4][2];
#pragma unroll
            for (int mi = 0; mi < 4; mi++) {
                const int rb = wm * 64 + mi * 16;
                ldsm_x4(af[mi][0], af[mi][1], af[mi][2], af[mi][3],
                        &As[buf][rb + a_row][kc + a_col]);
            }
#pragma unroll
            for (int ni = 0; ni < 4; ni++) {
                const int nb = wn * 32 + ni * 8;
                ldsm_x2t(bf[ni][0], bf[ni][1], &Bs[buf][kc + b_row][nb]);
            }
#pragma unroll
            for (int mi = 0; mi < 4; mi++)
#pragma unroll
                for (int ni = 0; ni < 4; ni++)
                    mma_bf16(acc[mi][ni][0], acc[mi][ni][1], acc[mi][ni][2], acc[mi][ni][3],
                             af[mi][0], af[mi][1], af[mi][2], af[mi][3],
                             bf[ni][0], bf[ni][1]);
        }
        __syncthreads();
    }

    // epilogue: bias (+gelu)
#pragma unroll
    for (int mi = 0; mi < 4; mi++) {
        const int r0g = row0 + wm * 64 + mi * 16 + g;
#pragma unroll
        for (int ni = 0; ni < 4; ni++) {
            const int c = col0 + wn * 32 + ni * 8 + t4 * 2;
            const float bx = bias[c], by = bias[c + 1];
            float v0 = acc[mi][ni][0] + bx, v1 = acc[mi][ni][1] + by;
            float v2 = acc[mi][ni][2] + bx, v3 = acc[mi][ni][3] + by;
            if (DOGELU) {
                v0 = 0.5f * v0 * (1.f + erff(v0 * 0.70710678118654752f));
                v1 = 0.5f * v1 * (1.f + erff(v1 * 0.70710678118654752f));
                v2 = 0.5f * v2 * (1.f + erff(v2 * 0.70710678118654752f));
                v3 = 0.5f * v3 * (1.f + erff(v3 * 0.70710678118654752f));
            }
            if (OUTBF16) {
                __nv_bfloat16* C = (__nv_bfloat16*)Cv;
                *reinterpret_cast<__nv_bfloat162*>(C + (size_t)r0g * N + c) =
                    __floats2bfloat162_rn(v0, v1);
                *reinterpret_cast<__nv_bfloat162*>(C + (size_t)(r0g + 8) * N + c) =
                    __floats2bfloat162_rn(v2, v3);
            } else {
                float* C = (float*)Cv;
                *reinterpret_cast<float2*>(C + (size_t)r0g * N + c)       = make_float2(v0, v1);
                *reinterpret_cast<float2*>(C + (size_t)(r0g + 8) * N + c) = make_float2(v2, v3);
            }
        }
    }
}

// ---------------- fp32 -> bf16 conversion of x + weights (one kernel) ------------
#define Q_X   393216           // 6144*256/4
#define Q_WQ  (Q_X  + 49152)   // 256*768/4
#define Q_WO  (Q_WQ + 16384)   // 256*256/4
#define Q_W1  (Q_WO + 65536)   // 256*1024/4
#define Q_W2  (Q_W1 + 65536)   // 1024*256/4  -> total 589824 quads
__global__ __launch_bounds__(256) void cvt_kernel(
    const float* __restrict__ x,  const float* __restrict__ wq,
    const float* __restrict__ wo, const float* __restrict__ w1,
    const float* __restrict__ w2,
    __nv_bfloat16* __restrict__ xb, __nv_bfloat16* __restrict__ wqb,
    __nv_bfloat16* __restrict__ wob, __nv_bfloat16* __restrict__ w1b,
    __nv_bfloat16* __restrict__ w2b)
{
    int q = blockIdx.x * 256 + threadIdx.x;
    const float* s; __nv_bfloat16* d; int base;
    if      (q < Q_X)  { s = x;  d = xb;  base = 0;    }
    else if (q < Q_WQ) { s = wq; d = wqb; base = Q_X;  }
    else if (q < Q_WO) { s = wo; d = wob; base = Q_WQ; }
    else if (q < Q_W1) { s = w1; d = w1b; base = Q_WO; }
    else               { s = w2; d = w2b; base = Q_W1; }
    size_t i = (size_t)(q - base) * 4;
    float4 v = *reinterpret_cast<const float4*>(s + i);
    reinterpret_cast<__nv_bfloat162*>(d + i)[0] = __floats2bfloat162_rn(v.x, v.y);
    reinterpret_cast<__nv_bfloat162*>(d + i)[1] = __floats2bfloat162_rn(v.z, v.w);
}

// ---------------- segment attention: one warp per (token, head), bf16 out -------
__global__ __launch_bounds__(256) void attn_kernel(
    const float* __restrict__ qkv, const int* __restrict__ doc,
    __nv_bfloat16* __restrict__ out)
{
    int wg = (blockIdx.x * 256 + threadIdx.x) >> 5;
    int lane = threadIdx.x & 31;
    if (wg >= N_TOK * N_HEADS) return;
    int i = wg >> 2;
    int h = wg & 3;

    int my = doc[i];
    int lo = 0, hi = N_TOK;
    while (lo < hi) { int mid = (lo + hi) >> 1; if (doc[mid] < my) lo = mid + 1; else hi = mid; }
    int s = lo;
    lo = i; hi = N_TOK;
    while (lo < hi) { int mid = (lo + hi) >> 1; if (doc[mid] <= my) lo = mid + 1; else hi = mid; }
    int e = lo;

    const float* q = qkv + (size_t)i * (3 * D_MODEL) + h * D_HEAD;
    float q0 = q[lane], q1 = q[lane + 32];
    const float* kbase = qkv + D_MODEL + h * D_HEAD;
    const float* vbase = qkv + 2 * D_MODEL + h * D_HEAD;

    float m = -3.4e38f, sum = 0.f, o0 = 0.f, o1 = 0.f;
    for (int j = s; j < e; j++) {
        const float* kr = kbase + (size_t)j * (3 * D_MODEL);
        float d = q0 * kr[lane] + q1 * kr[lane + 32];
#pragma unroll
        for (int off = 16; off; off >>= 1) d += __shfl_xor_sync(0xffffffffu, d, off);
        float sc = d * 0.125f;
        float mn = fmaxf(m, sc);
        float corr = __expf(m - mn);
        float p = __expf(sc - mn);
        const float* vr = vbase + (size_t)j * (3 * D_MODEL);
        sum = sum * corr + p;
        o0 = o0 * corr + p * vr[lane];
        o1 = o1 * corr + p * vr[lane + 32];
        m = mn;
    }
    float inv = 1.f / sum;
    out[(size_t)i * D_MODEL + h * D_HEAD + lane]      = __float2bfloat16(o0 * inv);
    out[(size_t)i * D_MODEL + h * D_HEAD + lane + 32] = __float2bfloat16(o1 * inv);
}

// ---------------- residual + layernorm: warp per row; optional bf16 dual write --
template<bool DUAL>
__global__ __launch_bounds__(256) void ln_kernel(
    const float* __restrict__ y, const float* __restrict__ res,
    const float* __restrict__ gw, const float* __restrict__ bw,
    float* __restrict__ out, __nv_bfloat16* __restrict__ outb)
{
    int row = blockIdx.x * 8 + (threadIdx.x >> 5);
    int lane = threadIdx.x & 31;
    size_t base = (size_t)row * D_MODEL;

    float4 a0 = *reinterpret_cast<const float4*>(y + base + lane * 4);
    float4 r0 = *reinterpret_cast<const float4*>(res + base + lane * 4);
    float4 a1 = *reinterpret_cast<const float4*>(y + base + 128 + lane * 4);
    float4 r1 = *reinterpret_cast<const float4*>(res + base + 128 + lane * 4);
    a0.x += r0.x; a0.y += r0.y; a0.z += r0.z; a0.w += r0.w;
    a1.x += r1.x; a1.y += r1.y; a1.z += r1.z; a1.w += r1.w;

    float s  = a0.x + a0.y + a0.z + a0.w + a1.x + a1.y + a1.z + a1.w;
    float sq = a0.x*a0.x + a0.y*a0.y + a0.z*a0.z + a0.w*a0.w
             + a1.x*a1.x + a1.y*a1.y + a1.z*a1.z + a1.w*a1.w;
#pragma unroll
    for (int o = 16; o; o >>= 1) {
        s  += __shfl_xor_sync(0xffffffffu, s, o);
        sq += __shfl_xor_sync(0xffffffffu, sq, o);
    }
    float mu  = s * (1.f / D_MODEL);
    float var = sq * (1.f / D_MODEL) - mu * mu;
    float inv = rsqrtf(var + LN_EPS);

    float4 g0 = *reinterpret_cast<const float4*>(gw + lane * 4);
    float4 b0 = *reinterpret_cast<const float4*>(bw + lane * 4);
    float4 g1 = *reinterpret_cast<const float4*>(gw + 128 + lane * 4);
    float4 b1 = *reinterpret_cast<const float4*>(bw + 128 + lane * 4);
    float4 o0, o1;
    o0.x = (a0.x - mu) * inv * g0.x + b0.x;
    o0.y = (a0.y - mu) * inv * g0.y + b0.y;
    o0.z = (a0.z - mu) * inv * g0.z + b0.z;
    o0.w = (a0.w - mu) * inv * g0.w + b0.w;
    o1.x = (a1.x - mu) * inv * g1.x + b1.x;
    o1.y = (a1.y - mu) * inv * g1.y + b1.y;
    o1.z = (a1.z - mu) * inv * g1.z + b1.z;
    o1.w = (a1.w - mu) * inv * g1.w + b1.w;
    *reinterpret_cast<float4*>(out + base + lane * 4)       = o0;
    *reinterpret_cast<float4*>(out + base + 128 + lane * 4) = o1;
    if (DUAL) {
        reinterpret_cast<__nv_bfloat162*>(outb + base + lane * 4)[0] = __floats2bfloat162_rn(o0.x, o0.y);
        reinterpret_cast<__nv_bfloat162*>(outb + base + lane * 4)[1] = __floats2bfloat162_rn(o0.z, o0.w);
        reinterpret_cast<__nv_bfloat162*>(outb + base + 128 + lane * 4)[0] = __floats2bfloat162_rn(o1.x, o1.y);
        reinterpret_cast<__nv_bfloat162*>(outb + base + 128 + lane * 4)[1] = __floats2bfloat162_rn(o1.z, o1.w);
    }
}

// ---------------- launch ---------------------------------------------------------
extern "C" void kernel_launch(void* const* d_in, const int* in_sizes, int n_in,
                              void* d_out, int out_size)
{
    const float* x      = (const float*)d_in[0];
    const int*   doc    = (const int*)  d_in[1];
    const float* qkv_w  = (const float*)d_in[2];
    const float* qkv_b  = (const float*)d_in[3];
    const float* out_w  = (const float*)d_in[4];
    const float* out_b  = (const float*)d_in[5];
    const float* ff_w1  = (const float*)d_in[6];
    const float* ff_b1  = (const float*)d_in[7];
    const float* ff_w2  = (const float*)d_in[8];
    const float* ff_b2  = (const float*)d_in[9];
    const float* ln1_g  = (const float*)d_in[10];
    const float* ln1_b  = (const float*)d_in[11];
    const float* ln2_g  = (const float*)d_in[12];
    const float* ln2_b  = (const float*)d_in[13];
    float* out = (float*)d_out;

    float *qkv, *x1, *tmp;
    __nv_bfloat16 *xb, *attnb, *x1b, *ffhb, *wq, *wo, *w1, *w2;
    cudaGetSymbolAddress((void**)&qkv,   g_qkv);
    cudaGetSymbolAddress((void**)&x1,    g_x1);
    cudaGetSymbolAddress((void**)&tmp,   g_tmp);
    cudaGetSymbolAddress((void**)&xb,    g_xb);
    cudaGetSymbolAddress((void**)&attnb, g_attnb);
    cudaGetSymbolAddress((void**)&x1b,   g_x1b);
    cudaGetSymbolAddress((void**)&ffhb,  g_ffhb);
    cudaGetSymbolAddress((void**)&wq,    g_wq);
    cudaGetSymbolAddress((void**)&wo,    g_wo);
    cudaGetSymbolAddress((void**)&w1,    g_w1);
    cudaGetSymbolAddress((void**)&w2,    g_w2);

    const int MT = N_TOK / 128;  // 48 row tiles

    cvt_kernel<<<Q_W2 / 256, 256>>>(x, qkv_w, out_w, ff_w1, ff_w2, xb, wq, wo, w1, w2);
    gemm_bf16_k<D_MODEL, 3 * D_MODEL, false, false><<<dim3(6, MT), 256>>>(xb, wq, qkv_b, qkv);
    attn_kernel<<<(N_TOK * N_HEADS) / 8, 256>>>(qkv, doc, attnb);
    gemm_bf16_k<D_MODEL, D_MODEL, false, false><<<dim3(2, MT), 256>>>(attnb, wo, out_b, tmp);
    ln_kernel<true><<<N_TOK / 8, 256>>>(tmp, x, ln1_g, ln1_b, x1, x1b);
    gemm_bf16_k<D_MODEL, D_FF, true, true><<<dim3(8, MT), 256>>>(x1b, w1, ff_b1, ffhb);
    gemm_bf16_k<D_FF, D_MODEL, false, false><<<dim3(2, MT), 256>>>(ffhb, w2, ff_b2, tmp);
    ln_kernel<false><<<N_TOK / 8, 256>>>(tmp, x1, ln2_g, ln2_b, out, nullptr);
}

// round 8
// speedup vs baseline: 3.8333x; 1.0479x over previous
#include <cuda_runtime.h>
#include <cuda_bf16.h>
#include <math.h>

#define N_TOK 6144
#define D_MODEL 256
#define N_HEADS 4
#define D_HEAD 64
#define D_FF 1024
#define LN_EPS 1e-5f

// ---------------- scratch (static device globals; no allocation) ----------------
__device__ float g_qkv [N_TOK * 3 * D_MODEL];           // fp32 (attention reads)
__device__ float g_x1  [N_TOK * D_MODEL];
__device__ float g_tmp [N_TOK * D_MODEL];
__device__ __nv_bfloat16 g_xb   [N_TOK * D_MODEL];      // bf16 activations/weights
__device__ __nv_bfloat16 g_attnb[N_TOK * D_MODEL];
__device__ __nv_bfloat16 g_x1b  [N_TOK * D_MODEL];
__device__ __nv_bfloat16 g_ffhb [N_TOK * D_FF];
__device__ __nv_bfloat16 g_wq   [D_MODEL * 3 * D_MODEL];
__device__ __nv_bfloat16 g_wo   [D_MODEL * D_MODEL];
__device__ __nv_bfloat16 g_w1   [D_MODEL * D_FF];
__device__ __nv_bfloat16 g_w2   [D_FF * D_MODEL];

// ---------------- helpers --------------------------------------------------------
__device__ __forceinline__ void cp16(void* smem_dst, const void* gsrc) {
    unsigned d = (unsigned)__cvta_generic_to_shared(smem_dst);
    asm volatile("cp.async.cg.shared.global [%0], [%1], 16;\n" :: "r"(d), "l"(gsrc));
}
__device__ __forceinline__ void cp_commit() { asm volatile("cp.async.commit_group;\n"); }
template<int NLEFT>
__device__ __forceinline__ void cp_wait()   { asm volatile("cp.async.wait_group %0;\n" :: "n"(NLEFT)); }

__device__ __forceinline__ void ldsm_x4(unsigned& r0, unsigned& r1, unsigned& r2, unsigned& r3,
                                        const void* p) {
    unsigned a = (unsigned)__cvta_generic_to_shared(p);
    asm volatile("ldmatrix.sync.aligned.m8n8.x4.shared.b16 {%0,%1,%2,%3}, [%4];"
                 : "=r"(r0), "=r"(r1), "=r"(r2), "=r"(r3) : "r"(a));
}
__device__ __forceinline__ void ldsm_x2t(unsigned& r0, unsigned& r1, const void* p) {
    unsigned a = (unsigned)__cvta_generic_to_shared(p);
    asm volatile("ldmatrix.sync.aligned.m8n8.x2.trans.shared.b16 {%0,%1}, [%2];"
                 : "=r"(r0), "=r"(r1) : "r"(a));
}
__device__ __forceinline__ void mma_bf16(
    float& c0, float& c1, float& c2, float& c3,
    unsigned a0, unsigned a1, unsigned a2, unsigned a3,
    unsigned b0, unsigned b1)
{
    asm volatile(
        "mma.sync.aligned.m16n8k16.row.col.f32.bf16.bf16.f32 "
        "{%0,%1,%2,%3}, {%4,%5,%6,%7}, {%8,%9}, {%0,%1,%2,%3};\n"
        : "+f"(c0), "+f"(c1), "+f"(c2), "+f"(c3)
        : "r"(a0), "r"(a1), "r"(a2), "r"(a3), "r"(b0), "r"(b1));
}

// ---------------- bf16 tensor-core GEMM, 3-stage cp.async pipeline ---------------
// Block tile 128 x BN (BN=128 or 64), BK=32, dynamic smem. 8 warps.
// BN=128: warps 2(M)x4(N), warp tile 64x32.  BN=64: warps 4(M)x2(N), warp 32x32.
#define BK 32
#define A_STR 40    // bf16 words; 80B row stride -> conflict-free ldmatrix

// integral constants usable from both host and device (no function call)
template<int BN> struct GemmCfg {
    static constexpr int B_STR = (BN == 128) ? 136 : 72;
    static constexpr int SMEM  = (3 * 128 * A_STR + 3 * BK * B_STR) * 2;
};

template<int K, int N, int BN, bool DOGELU, bool OUTBF16>
__global__ __launch_bounds__(256, 2) void gemm_bf16_k(
    const __nv_bfloat16* __restrict__ A, const __nv_bfloat16* __restrict__ B,
    const float* __restrict__ bias, void* __restrict__ Cv)
{
    constexpr int B_STR   = GemmCfg<BN>::B_STR;
    constexpr int WARPS_N = (BN == 128) ? 4 : 2;
    constexpr int WARPS_M = 8 / WARPS_N;              // 2 or 4
    constexpr int WM = 128 / WARPS_M;                 // 64 or 32
    constexpr int WN = BN / WARPS_N;                  // 32
    constexpr int MI = WM / 16;                       // 4 or 2
    constexpr int NI = WN / 8;                        // 4

    extern __shared__ __nv_bfloat16 smdyn[];
    typedef __nv_bfloat16 (*AsT)[128][A_STR];
    typedef __nv_bfloat16 (*BsT)[BK][B_STR];
    AsT As = reinterpret_cast<AsT>(smdyn);
    BsT Bs = reinterpret_cast<BsT>(smdyn + 3 * 128 * A_STR);

    const int tid  = threadIdx.x;
    const int row0 = blockIdx.y * 128;
    const int col0 = blockIdx.x * BN;
    const int w    = tid >> 5;
    const int lane = tid & 31;
    const int wm = w % WARPS_M;
    const int wn = w / WARPS_M;
    const int g  = lane >> 2;
    const int t4 = lane & 3;

    float acc[MI][NI][4];
#pragma unroll
    for (int mi = 0; mi < MI; mi++)
#pragma unroll
        for (int ni = 0; ni < NI; ni++)
#pragma unroll
            for (int r = 0; r < 4; r++) acc[mi][ni][r] = 0.f;

    // staging indices: A = 512 8-elem chunks (2/thread); B = BK*BN/8 chunks
    const int ar0 = tid >> 2,         ac0 = (tid & 3) * 8;
    const int ar1 = (tid + 256) >> 2, ac1 = ((tid + 256) & 3) * 8;
    const int br0 = (BN == 128) ? (tid >> 4) : (tid >> 3);
    const int bc0 = (BN == 128) ? ((tid & 15) * 8) : ((tid & 7) * 8);
    const int br1 = (tid + 256) >> 4, bc1 = ((tid + 256) & 15) * 8;  // BN==128 only

    auto stage = [&](int kt, int buf) {
        cp16(&As[buf][ar0][ac0], A + (size_t)(row0 + ar0) * K + kt + ac0);
        cp16(&As[buf][ar1][ac1], A + (size_t)(row0 + ar1) * K + kt + ac1);
        cp16(&Bs[buf][br0][bc0], B + (size_t)(kt + br0) * N + col0 + bc0);
        if (BN == 128)
            cp16(&Bs[buf][br1][bc1], B + (size_t)(kt + br1) * N + col0 + bc1);
        cp_commit();
    };

    constexpr int T = K / BK;
    stage(0, 0);
    stage(BK, 1);

    // ldmatrix lane addressing
    const int a_row = lane & 15;
    const int a_col = ((lane >> 4) << 3);
    const int b_row = lane & 15;

    for (int t = 0; t < T; t++) {
        cp_wait<1>();            // stage t complete
        __syncthreads();         // also: all warps done computing t-1
        if (t + 2 < T) stage((t + 2) * BK, (t + 2) % 3);
        else cp_commit();        // keep group count in lockstep
        const int buf = t % 3;

#pragma unroll
        for (int ks = 0; ks < 2; ks++) {
            const int kc = ks * 16;
            unsigned af[MI][4], bf[NI][2];
#pragma unroll
            for (int mi = 0; mi < MI; mi++) {
                const int rb = wm * WM + mi * 16;
                ldsm_x4(af[mi][0], af[mi][1], af[mi][2], af[mi][3],
                        &As[buf][rb + a_row][kc + a_col]);
            }
#pragma unroll
            for (int ni = 0; ni < NI; ni++) {
                const int nb = wn * WN + ni * 8;
                ldsm_x2t(bf[ni][0], bf[ni][1], &Bs[buf][kc + b_row][nb]);
            }
#pragma unroll
            for (int mi = 0; mi < MI; mi++)
#pragma unroll
                for (int ni = 0; ni < NI; ni++)
                    mma_bf16(acc[mi][ni][0], acc[mi][ni][1], acc[mi][ni][2], acc[mi][ni][3],
                             af[mi][0], af[mi][1], af[mi][2], af[mi][3],
                             bf[ni][0], bf[ni][1]);
        }
    }

    // epilogue: bias (+gelu)
#pragma unroll
    for (int mi = 0; mi < MI; mi++) {
        const int r0g = row0 + wm * WM + mi * 16 + g;
#pragma unroll
        for (int ni = 0; ni < NI; ni++) {
            const int c = col0 + wn * WN + ni * 8 + t4 * 2;
            const float bx = bias[c], by = bias[c + 1];
            float v0 = acc[mi][ni][0] + bx, v1 = acc[mi][ni][1] + by;
            float v2 = acc[mi][ni][2] + bx, v3 = acc[mi][ni][3] + by;
            if (DOGELU) {
                v0 = 0.5f * v0 * (1.f + erff(v0 * 0.70710678118654752f));
                v1 = 0.5f * v1 * (1.f + erff(v1 * 0.70710678118654752f));
                v2 = 0.5f * v2 * (1.f + erff(v2 * 0.70710678118654752f));
                v3 = 0.5f * v3 * (1.f + erff(v3 * 0.70710678118654752f));
            }
            if (OUTBF16) {
                __nv_bfloat16* C = (__nv_bfloat16*)Cv;
                *reinterpret_cast<__nv_bfloat162*>(C + (size_t)r0g * N + c) =
                    __floats2bfloat162_rn(v0, v1);
                *reinterpret_cast<__nv_bfloat162*>(C + (size_t)(r0g + 8) * N + c) =
                    __floats2bfloat162_rn(v2, v3);
            } else {
                float* C = (float*)Cv;
                *reinterpret_cast<float2*>(C + (size_t)r0g * N + c)       = make_float2(v0, v1);
                *reinterpret_cast<float2*>(C + (size_t)(r0g + 8) * N + c) = make_float2(v2, v3);
            }
        }
    }
}

// ---------------- fp32 -> bf16 conversion of x + weights (one kernel) ------------
#define Q_X   393216           // 6144*256/4
#define Q_WQ  (Q_X  + 49152)   // 256*768/4
#define Q_WO  (Q_WQ + 16384)   // 256*256/4
#define Q_W1  (Q_WO + 65536)   // 256*1024/4
#define Q_W2  (Q_W1 + 65536)   // 1024*256/4  -> total 589824 quads
__global__ __launch_bounds__(256) void cvt_kernel(
    const float* __restrict__ x,  const float* __restrict__ wq,
    const float* __restrict__ wo, const float* __restrict__ w1,
    const float* __restrict__ w2,
    __nv_bfloat16* __restrict__ xb, __nv_bfloat16* __restrict__ wqb,
    __nv_bfloat16* __restrict__ wob, __nv_bfloat16* __restrict__ w1b,
    __nv_bfloat16* __restrict__ w2b)
{
    int q = blockIdx.x * 256 + threadIdx.x;
    const float* s; __nv_bfloat16* d; int base;
    if      (q < Q_X)  { s = x;  d = xb;  base = 0;    }
    else if (q < Q_WQ) { s = wq; d = wqb; base = Q_X;  }
    else if (q < Q_WO) { s = wo; d = wob; base = Q_WQ; }
    else if (q < Q_W1) { s = w1; d = w1b; base = Q_WO; }
    else               { s = w2; d = w2b; base = Q_W1; }
    size_t i = (size_t)(q - base) * 4;
    float4 v = *reinterpret_cast<const float4*>(s + i);
    reinterpret_cast<__nv_bfloat162*>(d + i)[0] = __floats2bfloat162_rn(v.x, v.y);
    reinterpret_cast<__nv_bfloat162*>(d + i)[1] = __floats2bfloat162_rn(v.z, v.w);
}

// ---------------- segment attention: one warp per (token, head), bf16 out -------
__global__ __launch_bounds__(256) void attn_kernel(
    const float* __restrict__ qkv, const int* __restrict__ doc,
    __nv_bfloat16* __restrict__ out)
{
    int wg = (blockIdx.x * 256 + threadIdx.x) >> 5;
    int lane = threadIdx.x & 31;
    if (wg >= N_TOK * N_HEADS) return;
    int i = wg >> 2;
    int h = wg & 3;

    int my = doc[i];
    int lo = 0, hi = N_TOK;
    while (lo < hi) { int mid = (lo + hi) >> 1; if (doc[mid] < my) lo = mid + 1; else hi = mid; }
    int s = lo;
    lo = i; hi = N_TOK;
    while (lo < hi) { int mid = (lo + hi) >> 1; if (doc[mid] <= my) lo = mid + 1; else hi = mid; }
    int e = lo;

    const float* q = qkv + (size_t)i * (3 * D_MODEL) + h * D_HEAD;
    float q0 = q[lane], q1 = q[lane + 32];
    const float* kbase = qkv + D_MODEL + h * D_HEAD;
    const float* vbase = qkv + 2 * D_MODEL + h * D_HEAD;

    float m = -3.4e38f, sum = 0.f, o0 = 0.f, o1 = 0.f;
    for (int j = s; j < e; j++) {
        const float* kr = kbase + (size_t)j * (3 * D_MODEL);
        float d = q0 * kr[lane] + q1 * kr[lane + 32];
#pragma unroll
        for (int off = 16; off; off >>= 1) d += __shfl_xor_sync(0xffffffffu, d, off);
        float sc = d * 0.125f;
        float mn = fmaxf(m, sc);
        float corr = __expf(m - mn);
        float p = __expf(sc - mn);
        const float* vr = vbase + (size_t)j * (3 * D_MODEL);
        sum = sum * corr + p;
        o0 = o0 * corr + p * vr[lane];
        o1 = o1 * corr + p * vr[lane + 32];
        m = mn;
    }
    float inv = 1.f / sum;
    out[(size_t)i * D_MODEL + h * D_HEAD + lane]      = __float2bfloat16(o0 * inv);
    out[(size_t)i * D_MODEL + h * D_HEAD + lane + 32] = __float2bfloat16(o1 * inv);
}

// ---------------- residual + layernorm: warp per row; optional bf16 dual write --
template<bool DUAL>
__global__ __launch_bounds__(256) void ln_kernel(
    const float* __restrict__ y, const float* __restrict__ res,
    const float* __restrict__ gw, const float* __restrict__ bw,
    float* __restrict__ out, __nv_bfloat16* __restrict__ outb)
{
    int row = blockIdx.x * 8 + (threadIdx.x >> 5);
    int lane = threadIdx.x & 31;
    size_t base = (size_t)row * D_MODEL;

    float4 a0 = *reinterpret_cast<const float4*>(y + base + lane * 4);
    float4 r0 = *reinterpret_cast<const float4*>(res + base + lane * 4);
    float4 a1 = *reinterpret_cast<const float4*>(y + base + 128 + lane * 4);
    float4 r1 = *reinterpret_cast<const float4*>(res + base + 128 + lane * 4);
    a0.x += r0.x; a0.y += r0.y; a0.z += r0.z; a0.w += r0.w;
    a1.x += r1.x; a1.y += r1.y; a1.z += r1.z; a1.w += r1.w;

    float s  = a0.x + a0.y + a0.z + a0.w + a1.x + a1.y + a1.z + a1.w;
    float sq = a0.x*a0.x + a0.y*a0.y + a0.z*a0.z + a0.w*a0.w
             + a1.x*a1.x + a1.y*a1.y + a1.z*a1.z + a1.w*a1.w;
#pragma unroll
    for (int o = 16; o; o >>= 1) {
        s  += __shfl_xor_sync(0xffffffffu, s, o);
        sq += __shfl_xor_sync(0xffffffffu, sq, o);
    }
    float mu  = s * (1.f / D_MODEL);
    float var = sq * (1.f / D_MODEL) - mu * mu;
    float inv = rsqrtf(var + LN_EPS);

    float4 g0 = *reinterpret_cast<const float4*>(gw + lane * 4);
    float4 b0 = *reinterpret_cast<const float4*>(bw + lane * 4);
    float4 g1 = *reinterpret_cast<const float4*>(gw + 128 + lane * 4);
    float4 b1 = *reinterpret_cast<const float4*>(bw + 128 + lane * 4);
    float4 o0, o1;
    o0.x = (a0.x - mu) * inv * g0.x + b0.x;
    o0.y = (a0.y - mu) * inv * g0.y + b0.y;
    o0.z = (a0.z - mu) * inv * g0.z + b0.z;
    o0.w = (a0.w - mu) * inv * g0.w + b0.w;
    o1.x = (a1.x - mu) * inv * g1.x + b1.x;
    o1.y = (a1.y - mu) * inv * g1.y + b1.y;
    o1.z = (a1.z - mu) * inv * g1.z + b1.z;
    o1.w = (a1.w - mu) * inv * g1.w + b1.w;
    *reinterpret_cast<float4*>(out + base + lane * 4)       = o0;
    *reinterpret_cast<float4*>(out + base + 128 + lane * 4) = o1;
    if (DUAL) {
        reinterpret_cast<__nv_bfloat162*>(outb + base + lane * 4)[0] = __floats2bfloat162_rn(o0.x, o0.y);
        reinterpret_cast<__nv_bfloat162*>(outb + base + lane * 4)[1] = __floats2bfloat162_rn(o0.z, o0.w);
        reinterpret_cast<__nv_bfloat162*>(outb + base + 128 + lane * 4)[0] = __floats2bfloat162_rn(o1.x, o1.y);
        reinterpret_cast<__nv_bfloat162*>(outb + base + 128 + lane * 4)[1] = __floats2bfloat162_rn(o1.z, o1.w);
    }
}

// ---------------- launch ---------------------------------------------------------
extern "C" void kernel_launch(void* const* d_in, const int* in_sizes, int n_in,
                              void* d_out, int out_size)
{
    const float* x      = (const float*)d_in[0];
    const int*   doc    = (const int*)  d_in[1];
    const float* qkv_w  = (const float*)d_in[2];
    const float* qkv_b  = (const float*)d_in[3];
    const float* out_w  = (const float*)d_in[4];
    const float* out_b  = (const float*)d_in[5];
    const float* ff_w1  = (const float*)d_in[6];
    const float* ff_b1  = (const float*)d_in[7];
    const float* ff_w2  = (const float*)d_in[8];
    const float* ff_b2  = (const float*)d_in[9];
    const float* ln1_g  = (const float*)d_in[10];
    const float* ln1_b  = (const float*)d_in[11];
    const float* ln2_g  = (const float*)d_in[12];
    const float* ln2_b  = (const float*)d_in[13];
    float* out = (float*)d_out;

    float *qkv, *x1, *tmp;
    __nv_bfloat16 *xb, *attnb, *x1b, *ffhb, *wq, *wo, *w1, *w2;
    cudaGetSymbolAddress((void**)&qkv,   g_qkv);
    cudaGetSymbolAddress((void**)&x1,    g_x1);
    cudaGetSymbolAddress((void**)&tmp,   g_tmp);
    cudaGetSymbolAddress((void**)&xb,    g_xb);
    cudaGetSymbolAddress((void**)&attnb, g_attnb);
    cudaGetSymbolAddress((void**)&x1b,   g_x1b);
    cudaGetSymbolAddress((void**)&ffhb,  g_ffhb);
    cudaGetSymbolAddress((void**)&wq,    g_wq);
    cudaGetSymbolAddress((void**)&wo,    g_wo);
    cudaGetSymbolAddress((void**)&w1,    g_w1);
    cudaGetSymbolAddress((void**)&w2,    g_w2);

    const int MT = N_TOK / 128;  // 48 row tiles

    // opt-in to >48KB dynamic smem for the wide-tile kernels (idempotent host calls)
    constexpr int SM128 = GemmCfg<128>::SMEM;   // 56832
    constexpr int SM64  = GemmCfg<64>::SMEM;    // 44544
    cudaFuncSetAttribute((const void*)gemm_bf16_k<D_MODEL, 3 * D_MODEL, 128, false, false>,
                         cudaFuncAttributeMaxDynamicSharedMemorySize, SM128);
    cudaFuncSetAttribute((const void*)gemm_bf16_k<D_MODEL, D_FF, 128, true, true>,
                         cudaFuncAttributeMaxDynamicSharedMemorySize, SM128);
    cudaFuncSetAttribute((const void*)gemm_bf16_k<D_MODEL, D_MODEL, 64, false, false>,
                         cudaFuncAttributeMaxDynamicSharedMemorySize, SM64);
    cudaFuncSetAttribute((const void*)gemm_bf16_k<D_FF, D_MODEL, 64, false, false>,
                         cudaFuncAttributeMaxDynamicSharedMemorySize, SM64);

    cvt_kernel<<<Q_W2 / 256, 256>>>(x, qkv_w, out_w, ff_w1, ff_w2, xb, wq, wo, w1, w2);
    // QKV: N=768, BN=128 -> grid 6x48=288
    gemm_bf16_k<D_MODEL, 3 * D_MODEL, 128, false, false><<<dim3(6, MT), 256, SM128>>>(xb, wq, qkv_b, qkv);
    attn_kernel<<<(N_TOK * N_HEADS) / 8, 256>>>(qkv, doc, attnb);
    // out-proj: N=256, BN=64 -> grid 4x48=192
    gemm_bf16_k<D_MODEL, D_MODEL, 64, false, false><<<dim3(4, MT), 256, SM64>>>(attnb, wo, out_b, tmp);
    ln_kernel<true><<<N_TOK / 8, 256>>>(tmp, x, ln1_g, ln1_b, x1, x1b);
    // FF1: N=1024, BN=128 -> grid 8x48=384
    gemm_bf16_k<D_MODEL, D_FF, 128, true, true><<<dim3(8, MT), 256, SM128>>>(x1b, w1, ff_b1, ffhb);
    // FF2: N=256, BN=64 -> grid 4x48=192
    gemm_bf16_k<D_FF, D_MODEL, 64, false, false><<<dim3(4, MT), 256, SM64>>>(ffhb, w2, ff_b2, tmp);
    ln_kernel<false><<<N_TOK / 8, 256>>>(tmp, x1, ln2_g, ln2_b, out, nullptr);
}

// round 9
// speedup vs baseline: 4.0663x; 1.0608x over previous
#include <cuda_runtime.h>
#include <cuda_bf16.h>
#include <math.h>

#define N_TOK 6144
#define D_MODEL 256
#define N_HEADS 4
#define D_HEAD 64
#define D_FF 1024
#define LN_EPS 1e-5f

// ---------------- scratch (static device globals; no allocation) ----------------
__device__ float g_qkv [N_TOK * 3 * D_MODEL];           // fp32 (attention reads)
__device__ float g_x1  [N_TOK * D_MODEL];
__device__ float g_tmp [N_TOK * D_MODEL];
__device__ __nv_bfloat16 g_xb   [N_TOK * D_MODEL];      // bf16 activations/weights
__device__ __nv_bfloat16 g_attnb[N_TOK * D_MODEL];
__device__ __nv_bfloat16 g_x1b  [N_TOK * D_MODEL];
__device__ __nv_bfloat16 g_ffhb [N_TOK * D_FF];
__device__ __nv_bfloat16 g_wq   [D_MODEL * 3 * D_MODEL];
__device__ __nv_bfloat16 g_wo   [D_MODEL * D_MODEL];
__device__ __nv_bfloat16 g_w1   [D_MODEL * D_FF];
__device__ __nv_bfloat16 g_w2   [D_FF * D_MODEL];

// ---------------- helpers --------------------------------------------------------
__device__ __forceinline__ void cp16(void* smem_dst, const void* gsrc) {
    unsigned d = (unsigned)__cvta_generic_to_shared(smem_dst);
    asm volatile("cp.async.cg.shared.global [%0], [%1], 16;\n" :: "r"(d), "l"(gsrc));
}
__device__ __forceinline__ void cp_commit() { asm volatile("cp.async.commit_group;\n"); }
template<int NLEFT>
__device__ __forceinline__ void cp_wait()   { asm volatile("cp.async.wait_group %0;\n" :: "n"(NLEFT)); }

__device__ __forceinline__ void ldsm_x4(unsigned& r0, unsigned& r1, unsigned& r2, unsigned& r3,
                                        const void* p) {
    unsigned a = (unsigned)__cvta_generic_to_shared(p);
    asm volatile("ldmatrix.sync.aligned.m8n8.x4.shared.b16 {%0,%1,%2,%3}, [%4];"
                 : "=r"(r0), "=r"(r1), "=r"(r2), "=r"(r3) : "r"(a));
}
__device__ __forceinline__ void ldsm_x2t(unsigned& r0, unsigned& r1, const void* p) {
    unsigned a = (unsigned)__cvta_generic_to_shared(p);
    asm volatile("ldmatrix.sync.aligned.m8n8.x2.trans.shared.b16 {%0,%1}, [%2];"
                 : "=r"(r0), "=r"(r1) : "r"(a));
}
__device__ __forceinline__ void mma_bf16(
    float& c0, float& c1, float& c2, float& c3,
    unsigned a0, unsigned a1, unsigned a2, unsigned a3,
    unsigned b0, unsigned b1)
{
    asm volatile(
        "mma.sync.aligned.m16n8k16.row.col.f32.bf16.bf16.f32 "
        "{%0,%1,%2,%3}, {%4,%5,%6,%7}, {%8,%9}, {%0,%1,%2,%3};\n"
        : "+f"(c0), "+f"(c1), "+f"(c2), "+f"(c3)
        : "r"(a0), "r"(a1), "r"(a2), "r"(a3), "r"(b0), "r"(b1));
}

// ---------------- bf16 tensor-core GEMM, 4-stage cp.async pipeline ---------------
// Block tile 128 x BN (BN=128 or 64), BK=32, dynamic smem. 8 warps.
// BN=128: warps 2(M)x4(N), warp tile 64x32.  BN=64: warps 4(M)x2(N), warp 32x32.
#define BK 32
#define NSTG 4      // pipeline stages (3 groups in flight)
#define A_STR 40    // bf16 words; 80B row stride -> conflict-free ldmatrix

// integral constants usable from both host and device (no function call)
template<int BN> struct GemmCfg {
    static constexpr int B_STR = (BN == 128) ? 136 : 72;
    static constexpr int SMEM  = (NSTG * 128 * A_STR + NSTG * BK * B_STR) * 2;
};

template<int K, int N, int BN, bool DOGELU, bool OUTBF16>
__global__ __launch_bounds__(256, 2) void gemm_bf16_k(
    const __nv_bfloat16* __restrict__ A, const __nv_bfloat16* __restrict__ B,
    const float* __restrict__ bias, void* __restrict__ Cv)
{
    constexpr int B_STR   = GemmCfg<BN>::B_STR;
    constexpr int WARPS_N = (BN == 128) ? 4 : 2;
    constexpr int WARPS_M = 8 / WARPS_N;              // 2 or 4
    constexpr int WM = 128 / WARPS_M;                 // 64 or 32
    constexpr int WN = BN / WARPS_N;                  // 32
    constexpr int MI = WM / 16;                       // 4 or 2
    constexpr int NI = WN / 8;                        // 4

    extern __shared__ __nv_bfloat16 smdyn[];
    typedef __nv_bfloat16 (*AsT)[128][A_STR];
    typedef __nv_bfloat16 (*BsT)[BK][B_STR];
    AsT As = reinterpret_cast<AsT>(smdyn);
    BsT Bs = reinterpret_cast<BsT>(smdyn + NSTG * 128 * A_STR);

    const int tid  = threadIdx.x;
    const int row0 = blockIdx.y * 128;
    const int col0 = blockIdx.x * BN;
    const int w    = tid >> 5;
    const int lane = tid & 31;
    const int wm = w % WARPS_M;
    const int wn = w / WARPS_M;
    const int g  = lane >> 2;
    const int t4 = lane & 3;

    float acc[MI][NI][4];
#pragma unroll
    for (int mi = 0; mi < MI; mi++)
#pragma unroll
        for (int ni = 0; ni < NI; ni++)
#pragma unroll
            for (int r = 0; r < 4; r++) acc[mi][ni][r] = 0.f;

    // staging indices: A = 512 8-elem chunks (2/thread); B = BK*BN/8 chunks
    const int ar0 = tid >> 2,         ac0 = (tid & 3) * 8;
    const int ar1 = (tid + 256) >> 2, ac1 = ((tid + 256) & 3) * 8;
    const int br0 = (BN == 128) ? (tid >> 4) : (tid >> 3);
    const int bc0 = (BN == 128) ? ((tid & 15) * 8) : ((tid & 7) * 8);
    const int br1 = (tid + 256) >> 4, bc1 = ((tid + 256) & 15) * 8;  // BN==128 only

    auto stage = [&](int kt, int buf) {
        cp16(&As[buf][ar0][ac0], A + (size_t)(row0 + ar0) * K + kt + ac0);
        cp16(&As[buf][ar1][ac1], A + (size_t)(row0 + ar1) * K + kt + ac1);
        cp16(&Bs[buf][br0][bc0], B + (size_t)(kt + br0) * N + col0 + bc0);
        if (BN == 128)
            cp16(&Bs[buf][br1][bc1], B + (size_t)(kt + br1) * N + col0 + bc1);
        cp_commit();
    };

    constexpr int T = K / BK;
    static_assert(T >= 3, "need at least 3 k-tiles");
    stage(0, 0);
    stage(BK, 1);
    stage(2 * BK, 2);

    // ldmatrix lane addressing
    const int a_row = lane & 15;
    const int a_col = ((lane >> 4) << 3);
    const int b_row = lane & 15;

    for (int t = 0; t < T; t++) {
        cp_wait<2>();            // stage t complete (3 groups in flight)
        __syncthreads();         // also: all warps done computing t-NSTG+1
        if (t + 3 < T) stage((t + 3) * BK, (t + 3) & 3);
        else cp_commit();        // keep group count in lockstep
        const int buf = t & 3;

#pragma unroll
        for (int ks = 0; ks < 2; ks++) {
            const int kc = ks * 16;
            unsigned af[MI][4], bf[NI][2];
#pragma unroll
            for (int mi = 0; mi < MI; mi++) {
                const int rb = wm * WM + mi * 16;
                ldsm_x4(af[mi][0], af[mi][1], af[mi][2], af[mi][3],
                        &As[buf][rb + a_row][kc + a_col]);
            }
#pragma unroll
            for (int ni = 0; ni < NI; ni++) {
                const int nb = wn * WN + ni * 8;
                ldsm_x2t(bf[ni][0], bf[ni][1], &Bs[buf][kc + b_row][nb]);
            }
#pragma unroll
            for (int mi = 0; mi < MI; mi++)
#pragma unroll
                for (int ni = 0; ni < NI; ni++)
                    mma_bf16(acc[mi][ni][0], acc[mi][ni][1], acc[mi][ni][2], acc[mi][ni][3],
                             af[mi][0], af[mi][1], af[mi][2], af[mi][3],
                             bf[ni][0], bf[ni][1]);
        }
    }

    // epilogue: bias (+gelu)
#pragma unroll
    for (int mi = 0; mi < MI; mi++) {
        const int r0g = row0 + wm * WM + mi * 16 + g;
#pragma unroll
        for (int ni = 0; ni < NI; ni++) {
            const int c = col0 + wn * WN + ni * 8 + t4 * 2;
            const float bx = bias[c], by = bias[c + 1];
            float v0 = acc[mi][ni][0] + bx, v1 = acc[mi][ni][1] + by;
            float v2 = acc[mi][ni][2] + bx, v3 = acc[mi][ni][3] + by;
            if (DOGELU) {
                v0 = 0.5f * v0 * (1.f + erff(v0 * 0.70710678118654752f));
                v1 = 0.5f * v1 * (1.f + erff(v1 * 0.70710678118654752f));
                v2 = 0.5f * v2 * (1.f + erff(v2 * 0.70710678118654752f));
                v3 = 0.5f * v3 * (1.f + erff(v3 * 0.70710678118654752f));
            }
            if (OUTBF16) {
                __nv_bfloat16* C = (__nv_bfloat16*)Cv;
                *reinterpret_cast<__nv_bfloat162*>(C + (size_t)r0g * N + c) =
                    __floats2bfloat162_rn(v0, v1);
                *reinterpret_cast<__nv_bfloat162*>(C + (size_t)(r0g + 8) * N + c) =
                    __floats2bfloat162_rn(v2, v3);
            } else {
                float* C = (float*)Cv;
                *reinterpret_cast<float2*>(C + (size_t)r0g * N + c)       = make_float2(v0, v1);
                *reinterpret_cast<float2*>(C + (size_t)(r0g + 8) * N + c) = make_float2(v2, v3);
            }
        }
    }
}

// ---------------- fp32 -> bf16 conversion of x + weights (one kernel) ------------
#define Q_X   393216           // 6144*256/4
#define Q_WQ  (Q_X  + 49152)   // 256*768/4
#define Q_WO  (Q_WQ + 16384)   // 256*256/4
#define Q_W1  (Q_WO + 65536)   // 256*1024/4
#define Q_W2  (Q_W1 + 65536)   // 1024*256/4  -> total 589824 quads
__global__ __launch_bounds__(256) void cvt_kernel(
    const float* __restrict__ x,  const float* __restrict__ wq,
    const float* __restrict__ wo, const float* __restrict__ w1,
    const float* __restrict__ w2,
    __nv_bfloat16* __restrict__ xb, __nv_bfloat16* __restrict__ wqb,
    __nv_bfloat16* __restrict__ wob, __nv_bfloat16* __restrict__ w1b,
    __nv_bfloat16* __restrict__ w2b)
{
    int q = blockIdx.x * 256 + threadIdx.x;
    const float* s; __nv_bfloat16* d; int base;
    if      (q < Q_X)  { s = x;  d = xb;  base = 0;    }
    else if (q < Q_WQ) { s = wq; d = wqb; base = Q_X;  }
    else if (q < Q_WO) { s = wo; d = wob; base = Q_WQ; }
    else if (q < Q_W1) { s = w1; d = w1b; base = Q_WO; }
    else               { s = w2; d = w2b; base = Q_W1; }
    size_t i = (size_t)(q - base) * 4;
    float4 v = *reinterpret_cast<const float4*>(s + i);
    reinterpret_cast<__nv_bfloat162*>(d + i)[0] = __floats2bfloat162_rn(v.x, v.y);
    reinterpret_cast<__nv_bfloat162*>(d + i)[1] = __floats2bfloat162_rn(v.z, v.w);
}

// ---------------- segment attention: one warp per (token, head), bf16 out -------
// Segment bounds via one coalesced 32-token window + ballot (doc idx is sorted);
// scalar extension fallback for segments longer than the window (rare).
__global__ __launch_bounds__(256) void attn_kernel(
    const float* __restrict__ qkv, const int* __restrict__ doc,
    __nv_bfloat16* __restrict__ out)
{
    int wg = (blockIdx.x * 256 + threadIdx.x) >> 5;
    int lane = threadIdx.x & 31;
    if (wg >= N_TOK * N_HEADS) return;
    int i = wg >> 2;
    int h = wg & 3;

    const int my = doc[i];
    const int base = i - 16;
    const int idx = base + lane;
    int dv = -1;
    if (idx >= 0 && idx < N_TOK) dv = doc[idx];
    unsigned eq = __ballot_sync(0xffffffffu, dv == my);   // bit 16 (token i) always set

    // start: token after the highest non-equal position below bit 16
    unsigned below = ~eq & 0xffffu;                        // bits 0..15
    int s = (below == 0) ? base : base + (32 - __clz(below));
    // end: first non-equal position above bit 16
    unsigned above = ~eq & 0xfffe0000u;                    // bits 17..31
    int e = (above == 0) ? base + 32 : base + (__ffs(above) - 1);
    // rare fallback: segment extends past the window
    if (below == 0) { while (s > 0 && doc[s - 1] == my) s--; }
    if (above == 0) { while (e < N_TOK && doc[e] == my) e++; }

    const float* q = qkv + (size_t)i * (3 * D_MODEL) + h * D_HEAD;
    float q0 = q[lane], q1 = q[lane + 32];
    const float* kbase = qkv + D_MODEL + h * D_HEAD;
    const float* vbase = qkv + 2 * D_MODEL + h * D_HEAD;

    float m = -3.4e38f, sum = 0.f, o0 = 0.f, o1 = 0.f;
    for (int j = s; j < e; j++) {
        const float* kr = kbase + (size_t)j * (3 * D_MODEL);
        float d = q0 * kr[lane] + q1 * kr[lane + 32];
#pragma unroll
        for (int off = 16; off; off >>= 1) d += __shfl_xor_sync(0xffffffffu, d, off);
        float sc = d * 0.125f;
        float mn = fmaxf(m, sc);
        float corr = __expf(m - mn);
        float p = __expf(sc - mn);
        const float* vr = vbase + (size_t)j * (3 * D_MODEL);
        sum = sum * corr + p;
        o0 = o0 * corr + p * vr[lane];
        o1 = o1 * corr + p * vr[lane + 32];
        m = mn;
    }
    float inv = 1.f / sum;
    out[(size_t)i * D_MODEL + h * D_HEAD + lane]      = __float2bfloat16(o0 * inv);
    out[(size_t)i * D_MODEL + h * D_HEAD + lane + 32] = __float2bfloat16(o1 * inv);
}

// ---------------- residual + layernorm: warp per row; optional bf16 dual write --
template<bool DUAL>
__global__ __launch_bounds__(256) void ln_kernel(
    const float* __restrict__ y, const float* __restrict__ res,
    const float* __restrict__ gw, const float* __restrict__ bw,
    float* __restrict__ out, __nv_bfloat16* __restrict__ outb)
{
    int row = blockIdx.x * 8 + (threadIdx.x >> 5);
    int lane = threadIdx.x & 31;
    size_t base = (size_t)row * D_MODEL;

    float4 a0 = *reinterpret_cast<const float4*>(y + base + lane * 4);
    float4 r0 = *reinterpret_cast<const float4*>(res + base + lane * 4);
    float4 a1 = *reinterpret_cast<const float4*>(y + base + 128 + lane * 4);
    float4 r1 = *reinterpret_cast<const float4*>(res + base + 128 + lane * 4);
    a0.x += r0.x; a0.y += r0.y; a0.z += r0.z; a0.w += r0.w;
    a1.x += r1.x; a1.y += r1.y; a1.z += r1.z; a1.w += r1.w;

    float s  = a0.x + a0.y + a0.z + a0.w + a1.x + a1.y + a1.z + a1.w;
    float sq = a0.x*a0.x + a0.y*a0.y + a0.z*a0.z + a0.w*a0.w
             + a1.x*a1.x + a1.y*a1.y + a1.z*a1.z + a1.w*a1.w;
#pragma unroll
    for (int o = 16; o; o >>= 1) {
        s  += __shfl_xor_sync(0xffffffffu, s, o);
        sq += __shfl_xor_sync(0xffffffffu, sq, o);
    }
    float mu  = s * (1.f / D_MODEL);
    float var = sq * (1.f / D_MODEL) - mu * mu;
    float inv = rsqrtf(var + LN_EPS);

    float4 g0 = *reinterpret_cast<const float4*>(gw + lane * 4);
    float4 b0 = *reinterpret_cast<const float4*>(bw + lane * 4);
    float4 g1 = *reinterpret_cast<const float4*>(gw + 128 + lane * 4);
    float4 b1 = *reinterpret_cast<const float4*>(bw + 128 + lane * 4);
    float4 o0, o1;
    o0.x = (a0.x - mu) * inv * g0.x + b0.x;
    o0.y = (a0.y - mu) * inv * g0.y + b0.y;
    o0.z = (a0.z - mu) * inv * g0.z + b0.z;
    o0.w = (a0.w - mu) * inv * g0.w + b0.w;
    o1.x = (a1.x - mu) * inv * g1.x + b1.x;
    o1.y = (a1.y - mu) * inv * g1.y + b1.y;
    o1.z = (a1.z - mu) * inv * g1.z + b1.z;
    o1.w = (a1.w - mu) * inv * g1.w + b1.w;
    *reinterpret_cast<float4*>(out + base + lane * 4)       = o0;
    *reinterpret_cast<float4*>(out + base + 128 + lane * 4) = o1;
    if (DUAL) {
        reinterpret_cast<__nv_bfloat162*>(outb + base + lane * 4)[0] = __floats2bfloat162_rn(o0.x, o0.y);
        reinterpret_cast<__nv_bfloat162*>(outb + base + lane * 4)[1] = __floats2bfloat162_rn(o0.z, o0.w);
        reinterpret_cast<__nv_bfloat162*>(outb + base + 128 + lane * 4)[0] = __floats2bfloat162_rn(o1.x, o1.y);
        reinterpret_cast<__nv_bfloat162*>(outb + base + 128 + lane * 4)[1] = __floats2bfloat162_rn(o1.z, o1.w);
    }
}

// ---------------- launch ---------------------------------------------------------
extern "C" void kernel_launch(void* const* d_in, const int* in_sizes, int n_in,
                              void* d_out, int out_size)
{
    const float* x      = (const float*)d_in[0];
    const int*   doc    = (const int*)  d_in[1];
    const float* qkv_w  = (const float*)d_in[2];
    const float* qkv_b  = (const float*)d_in[3];
    const float* out_w  = (const float*)d_in[4];
    const float* out_b  = (const float*)d_in[5];
    const float* ff_w1  = (const float*)d_in[6];
    const float* ff_b1  = (const float*)d_in[7];
    const float* ff_w2  = (const float*)d_in[8];
    const float* ff_b2  = (const float*)d_in[9];
    const float* ln1_g  = (const float*)d_in[10];
    const float* ln1_b  = (const float*)d_in[11];
    const float* ln2_g  = (const float*)d_in[12];
    const float* ln2_b  = (const float*)d_in[13];
    float* out = (float*)d_out;

    float *qkv, *x1, *tmp;
    __nv_bfloat16 *xb, *attnb, *x1b, *ffhb, *wq, *wo, *w1, *w2;
    cudaGetSymbolAddress((void**)&qkv,   g_qkv);
    cudaGetSymbolAddress((void**)&x1,    g_x1);
    cudaGetSymbolAddress((void**)&tmp,   g_tmp);
    cudaGetSymbolAddress((void**)&xb,    g_xb);
    cudaGetSymbolAddress((void**)&attnb, g_attnb);
    cudaGetSymbolAddress((void**)&x1b,   g_x1b);
    cudaGetSymbolAddress((void**)&ffhb,  g_ffhb);
    cudaGetSymbolAddress((void**)&wq,    g_wq);
    cudaGetSymbolAddress((void**)&wo,    g_wo);
    cudaGetSymbolAddress((void**)&w1,    g_w1);
    cudaGetSymbolAddress((void**)&w2,    g_w2);

    const int MT = N_TOK / 128;  // 48 row tiles

    // opt-in to >48KB dynamic smem for the wide-tile kernels (idempotent host calls)
    constexpr int SM128 = GemmCfg<128>::SMEM;   // 75776
    constexpr int SM64  = GemmCfg<64>::SMEM;    // 59392
    cudaFuncSetAttribute((const void*)gemm_bf16_k<D_MODEL, 3 * D_MODEL, 128, false, false>,
                         cudaFuncAttributeMaxDynamicSharedMemorySize, SM128);
    cudaFuncSetAttribute((const void*)gemm_bf16_k<D_MODEL, D_FF, 128, true, true>,
                         cudaFuncAttributeMaxDynamicSharedMemorySize, SM128);
    cudaFuncSetAttribute((const void*)gemm_bf16_k<D_MODEL, D_MODEL, 64, false, false>,
                         cudaFuncAttributeMaxDynamicSharedMemorySize, SM64);
    cudaFuncSetAttribute((const void*)gemm_bf16_k<D_FF, D_MODEL, 64, false, false>,
                         cudaFuncAttributeMaxDynamicSharedMemorySize, SM64);

    cvt_kernel<<<Q_W2 / 256, 256>>>(x, qkv_w, out_w, ff_w1, ff_w2, xb, wq, wo, w1, w2);
    // QKV: N=768, BN=128 -> grid 6x48=288
    gemm_bf16_k<D_MODEL, 3 * D_MODEL, 128, false, false><<<dim3(6, MT), 256, SM128>>>(xb, wq, qkv_b, qkv);
    attn_kernel<<<(N_TOK * N_HEADS) / 8, 256>>>(qkv, doc, attnb);
    // out-proj: N=256, BN=64 -> grid 4x48=192
    gemm_bf16_k<D_MODEL, D_MODEL, 64, false, false><<<dim3(4, MT), 256, SM64>>>(attnb, wo, out_b, tmp);
    ln_kernel<true><<<N_TOK / 8, 256>>>(tmp, x, ln1_g, ln1_b, x1, x1b);
    // FF1: N=1024, BN=128 -> grid 8x48=384
    gemm_bf16_k<D_MODEL, D_FF, 128, true, true><<<dim3(8, MT), 256, SM128>>>(x1b, w1, ff_b1, ffhb);
    // FF2: N=256, BN=64 -> grid 4x48=192
    gemm_bf16_k<D_FF, D_MODEL, 64, false, false><<<dim3(4, MT), 256, SM64>>>(ffhb, w2, ff_b2, tmp);
    ln_kernel<false><<<N_TOK / 8, 256>>>(tmp, x1, ln2_g, ln2_b, out, nullptr);
}

// round 10
// speedup vs baseline: 4.2729x; 1.0508x over previous
#include <cuda_runtime.h>
#include <cuda_bf16.h>
#include <math.h>

#define N_TOK 6144
#define D_MODEL 256
#define N_HEADS 4
#define D_HEAD 64
#define D_FF 1024
#define LN_EPS 1e-5f

// ---------------- scratch (static device globals; no allocation) ----------------
__device__ float g_qkv [N_TOK * 3 * D_MODEL];           // fp32 (attention reads)
__device__ float g_x1  [N_TOK * D_MODEL];
__device__ float g_tmp [N_TOK * D_MODEL];
__device__ __nv_bfloat16 g_xb   [N_TOK * D_MODEL];      // bf16 activations/weights
__device__ __nv_bfloat16 g_attnb[N_TOK * D_MODEL];
__device__ __nv_bfloat16 g_x1b  [N_TOK * D_MODEL];
__device__ __nv_bfloat16 g_ffhb [N_TOK * D_FF];
__device__ __nv_bfloat16 g_wq   [D_MODEL * 3 * D_MODEL];
__device__ __nv_bfloat16 g_wo   [D_MODEL * D_MODEL];
__device__ __nv_bfloat16 g_w1   [D_MODEL * D_FF];
__device__ __nv_bfloat16 g_w2   [D_FF * D_MODEL];

// ---------------- helpers --------------------------------------------------------
__device__ __forceinline__ void cp16(void* smem_dst, const void* gsrc) {
    unsigned d = (unsigned)__cvta_generic_to_shared(smem_dst);
    asm volatile("cp.async.cg.shared.global [%0], [%1], 16;\n" :: "r"(d), "l"(gsrc));
}
__device__ __forceinline__ void cp_commit() { asm volatile("cp.async.commit_group;\n"); }
template<int NLEFT>
__device__ __forceinline__ void cp_wait()   { asm volatile("cp.async.wait_group %0;\n" :: "n"(NLEFT)); }

__device__ __forceinline__ void ldsm_x4(unsigned& r0, unsigned& r1, unsigned& r2, unsigned& r3,
                                        const void* p) {
    unsigned a = (unsigned)__cvta_generic_to_shared(p);
    asm volatile("ldmatrix.sync.aligned.m8n8.x4.shared.b16 {%0,%1,%2,%3}, [%4];"
                 : "=r"(r0), "=r"(r1), "=r"(r2), "=r"(r3) : "r"(a));
}
__device__ __forceinline__ void ldsm_x2t(unsigned& r0, unsigned& r1, const void* p) {
    unsigned a = (unsigned)__cvta_generic_to_shared(p);
    asm volatile("ldmatrix.sync.aligned.m8n8.x2.trans.shared.b16 {%0,%1}, [%2];"
                 : "=r"(r0), "=r"(r1) : "r"(a));
}
__device__ __forceinline__ void mma_bf16(
    float& c0, float& c1, float& c2, float& c3,
    unsigned a0, unsigned a1, unsigned a2, unsigned a3,
    unsigned b0, unsigned b1)
{
    asm volatile(
        "mma.sync.aligned.m16n8k16.row.col.f32.bf16.bf16.f32 "
        "{%0,%1,%2,%3}, {%4,%5,%6,%7}, {%8,%9}, {%0,%1,%2,%3};\n"
        : "+f"(c0), "+f"(c1), "+f"(c2), "+f"(c3)
        : "r"(a0), "r"(a1), "r"(a2), "r"(a3), "r"(b0), "r"(b1));
}

// ---------------- bf16 tensor-core GEMM, BK=64, 3-stage cp.async pipeline --------
// Block tile BM x BN, 8 warps as 2(M) x 4(N). Warp tile (BM/2) x (BN/4).
// Small config (BM=BN=64) register-double-buffers ldmatrix fragments and runs
// 3 CTAs/SM; big config (128x128) runs 2 CTAs/SM.
#define BK 64
#define NSTG 3
#define A_STR 72    // 64 + 8 pad, words; stride 144B -> conflict-free ldmatrix

template<int BM, int BN> struct GemmCfg {
    static constexpr int B_STR = (BN == 128) ? 136 : 72;
    static constexpr int SMEM  = (NSTG * BM * A_STR + NSTG * BK * B_STR) * 2;
};

template<int K, int N, int BM, int BN, bool DOGELU, bool OUTBF16>
__global__ __launch_bounds__(256, (BM == 128) ? 2 : 3) void gemm_bf16_k(
    const __nv_bfloat16* __restrict__ A, const __nv_bfloat16* __restrict__ B,
    const float* __restrict__ bias, void* __restrict__ Cv)
{
    constexpr int B_STR = GemmCfg<BM, BN>::B_STR;
    constexpr int WM = BM / 2;                 // 64 or 32
    constexpr int WN = BN / 4;                 // 32 or 16
    constexpr int MI = WM / 16;                // 4 or 2
    constexpr int NI = WN / 8;                 // 4 or 2
    constexpr int KS = BK / 16;                // 4
    constexpr bool DB = (MI * NI <= 4);        // frag double-buffer on small config

    extern __shared__ __nv_bfloat16 smdyn[];
    typedef __nv_bfloat16 (*AsT)[BM][A_STR];
    typedef __nv_bfloat16 (*BsT)[BK][B_STR];
    AsT As = reinterpret_cast<AsT>(smdyn);
    BsT Bs = reinterpret_cast<BsT>(smdyn + NSTG * BM * A_STR);

    const int tid  = threadIdx.x;
    const int row0 = blockIdx.y * BM;
    const int col0 = blockIdx.x * BN;
    const int w    = tid >> 5;
    const int lane = tid & 31;
    const int wm = w & 1;
    const int wn = w >> 1;
    const int g  = lane >> 2;
    const int t4 = lane & 3;

    float acc[MI][NI][4];
#pragma unroll
    for (int mi = 0; mi < MI; mi++)
#pragma unroll
        for (int ni = 0; ni < NI; ni++)
#pragma unroll
            for (int r = 0; r < 4; r++) acc[mi][ni][r] = 0.f;

    auto stage = [&](int kt, int buf) {
#pragma unroll
        for (int c = tid; c < BM * 8; c += 256) {           // A: BM x 64 / 8-elem chunks
            int r = c >> 3, col = (c & 7) * 8;
            cp16(&As[buf][r][col], A + (size_t)(row0 + r) * K + kt + col);
        }
#pragma unroll
        for (int c = tid; c < 8 * BN; c += 256) {           // B: 64 x BN / 8-elem chunks
            int r = c / (BN / 8), col = (c % (BN / 8)) * 8;
            cp16(&Bs[buf][r][col], B + (size_t)(kt + r) * N + col0 + col);
        }
        cp_commit();
    };

    constexpr int T = K / BK;
    static_assert(T >= 2, "need at least 2 k-slabs");
    stage(0, 0);
    stage(BK, 1);

    // ldmatrix lane addressing
    const int a_row = lane & 15;
    const int a_col = ((lane >> 4) << 3);
    const int b_row = lane & 15;

    auto load_frags = [&](unsigned (&af)[MI][4], unsigned (&bf)[NI][2], int buf, int ks) {
        const int kc = ks * 16;
#pragma unroll
        for (int mi = 0; mi < MI; mi++)
            ldsm_x4(af[mi][0], af[mi][1], af[mi][2], af[mi][3],
                    &As[buf][wm * WM + mi * 16 + a_row][kc + a_col]);
#pragma unroll
        for (int ni = 0; ni < NI; ni++)
            ldsm_x2t(bf[ni][0], bf[ni][1], &Bs[buf][kc + b_row][wn * WN + ni * 8]);
    };
    auto mma_all = [&](unsigned (&af)[MI][4], unsigned (&bf)[NI][2]) {
#pragma unroll
        for (int mi = 0; mi < MI; mi++)
#pragma unroll
            for (int ni = 0; ni < NI; ni++)
                mma_bf16(acc[mi][ni][0], acc[mi][ni][1], acc[mi][ni][2], acc[mi][ni][3],
                         af[mi][0], af[mi][1], af[mi][2], af[mi][3],
                         bf[ni][0], bf[ni][1]);
    };

    for (int t = 0; t < T; t++) {
        cp_wait<1>();            // slab t resident
        __syncthreads();
        if (t + 2 < T) stage((t + 2) * BK, (t + 2) % 3);
        else cp_commit();        // keep group count in lockstep
        const int buf = t % 3;

        if (DB) {
            unsigned af[2][MI][4], bf[2][NI][2];
            load_frags(af[0], bf[0], buf, 0);
#pragma unroll
            for (int ks = 0; ks < KS; ks++) {
                const int cur = ks & 1;
                if (ks + 1 < KS) load_frags(af[cur ^ 1], bf[cur ^ 1], buf, ks + 1);
                mma_all(af[cur], bf[cur]);
            }
        } else {
#pragma unroll
            for (int ks = 0; ks < KS; ks++) {
                unsigned af[MI][4], bf[NI][2];
                load_frags(af, bf, buf, ks);
                mma_all(af, bf);
            }
        }
    }

    // epilogue: bias (+gelu)
#pragma unroll
    for (int mi = 0; mi < MI; mi++) {
        const int r0g = row0 + wm * WM + mi * 16 + g;
#pragma unroll
        for (int ni = 0; ni < NI; ni++) {
            const int c = col0 + wn * WN + ni * 8 + t4 * 2;
            const float bx = bias[c], by = bias[c + 1];
            float v0 = acc[mi][ni][0] + bx, v1 = acc[mi][ni][1] + by;
            float v2 = acc[mi][ni][2] + bx, v3 = acc[mi][ni][3] + by;
            if (DOGELU) {
                v0 = 0.5f * v0 * (1.f + erff(v0 * 0.70710678118654752f));
                v1 = 0.5f * v1 * (1.f + erff(v1 * 0.70710678118654752f));
                v2 = 0.5f * v2 * (1.f + erff(v2 * 0.70710678118654752f));
                v3 = 0.5f * v3 * (1.f + erff(v3 * 0.70710678118654752f));
            }
            if (OUTBF16) {
                __nv_bfloat16* C = (__nv_bfloat16*)Cv;
                *reinterpret_cast<__nv_bfloat162*>(C + (size_t)r0g * N + c) =
                    __floats2bfloat162_rn(v0, v1);
                *reinterpret_cast<__nv_bfloat162*>(C + (size_t)(r0g + 8) * N + c) =
                    __floats2bfloat162_rn(v2, v3);
            } else {
                float* C = (float*)Cv;
                *reinterpret_cast<float2*>(C + (size_t)r0g * N + c)       = make_float2(v0, v1);
                *reinterpret_cast<float2*>(C + (size_t)(r0g + 8) * N + c) = make_float2(v2, v3);
            }
        }
    }
}

// ---------------- fp32 -> bf16 conversion of x + weights (one kernel) ------------
#define Q_X   393216           // 6144*256/4
#define Q_WQ  (Q_X  + 49152)   // 256*768/4
#define Q_WO  (Q_WQ + 16384)   // 256*256/4
#define Q_W1  (Q_WO + 65536)   // 256*1024/4
#define Q_W2  (Q_W1 + 65536)   // 1024*256/4  -> total 589824 quads
__global__ __launch_bounds__(256) void cvt_kernel(
    const float* __restrict__ x,  const float* __restrict__ wq,
    const float* __restrict__ wo, const float* __restrict__ w1,
    const float* __restrict__ w2,
    __nv_bfloat16* __restrict__ xb, __nv_bfloat16* __restrict__ wqb,
    __nv_bfloat16* __restrict__ wob, __nv_bfloat16* __restrict__ w1b,
    __nv_bfloat16* __restrict__ w2b)
{
    int q = blockIdx.x * 256 + threadIdx.x;
    const float* s; __nv_bfloat16* d; int base;
    if      (q < Q_X)  { s = x;  d = xb;  base = 0;    }
    else if (q < Q_WQ) { s = wq; d = wqb; base = Q_X;  }
    else if (q < Q_WO) { s = wo; d = wob; base = Q_WQ; }
    else if (q < Q_W1) { s = w1; d = w1b; base = Q_WO; }
    else               { s = w2; d = w2b; base = Q_W1; }
    size_t i = (size_t)(q - base) * 4;
    float4 v = *reinterpret_cast<const float4*>(s + i);
    reinterpret_cast<__nv_bfloat162*>(d + i)[0] = __floats2bfloat162_rn(v.x, v.y);
    reinterpret_cast<__nv_bfloat162*>(d + i)[1] = __floats2bfloat162_rn(v.z, v.w);
}

// ---------------- segment attention: one warp per (token, head), bf16 out -------
// Segment bounds via one coalesced 32-token window + ballot (doc idx is sorted);
// scalar extension fallback for segments longer than the window (rare).
__global__ __launch_bounds__(256) void attn_kernel(
    const float* __restrict__ qkv, const int* __restrict__ doc,
    __nv_bfloat16* __restrict__ out)
{
    int wg = (blockIdx.x * 256 + threadIdx.x) >> 5;
    int lane = threadIdx.x & 31;
    if (wg >= N_TOK * N_HEADS) return;
    int i = wg >> 2;
    int h = wg & 3;

    const int my = doc[i];
    const int base = i - 16;
    const int idx = base + lane;
    int dv = -1;
    if (idx >= 0 && idx < N_TOK) dv = doc[idx];
    unsigned eq = __ballot_sync(0xffffffffu, dv == my);   // bit 16 (token i) always set

    unsigned below = ~eq & 0xffffu;                        // bits 0..15
    int s = (below == 0) ? base : base + (32 - __clz(below));
    unsigned above = ~eq & 0xfffe0000u;                    // bits 17..31
    int e = (above == 0) ? base + 32 : base + (__ffs(above) - 1);
    if (below == 0) { while (s > 0 && doc[s - 1] == my) s--; }
    if (above == 0) { while (e < N_TOK && doc[e] == my) e++; }

    const float* q = qkv + (size_t)i * (3 * D_MODEL) + h * D_HEAD;
    float q0 = q[lane], q1 = q[lane + 32];
    const float* kbase = qkv + D_MODEL + h * D_HEAD;
    const float* vbase = qkv + 2 * D_MODEL + h * D_HEAD;

    float m = -3.4e38f, sum = 0.f, o0 = 0.f, o1 = 0.f;
    for (int j = s; j < e; j++) {
        const float* kr = kbase + (size_t)j * (3 * D_MODEL);
        float d = q0 * kr[lane] + q1 * kr[lane + 32];
#pragma unroll
        for (int off = 16; off; off >>= 1) d += __shfl_xor_sync(0xffffffffu, d, off);
        float sc = d * 0.125f;
        float mn = fmaxf(m, sc);
        float corr = __expf(m - mn);
        float p = __expf(sc - mn);
        const float* vr = vbase + (size_t)j * (3 * D_MODEL);
        sum = sum * corr + p;
        o0 = o0 * corr + p * vr[lane];
        o1 = o1 * corr + p * vr[lane + 32];
        m = mn;
    }
    float inv = 1.f / sum;
    out[(size_t)i * D_MODEL + h * D_HEAD + lane]      = __float2bfloat16(o0 * inv);
    out[(size_t)i * D_MODEL + h * D_HEAD + lane + 32] = __float2bfloat16(o1 * inv);
}

// ---------------- residual + layernorm: warp per row; optional bf16 dual write --
template<bool DUAL>
__global__ __launch_bounds__(256) void ln_kernel(
    const float* __restrict__ y, const float* __restrict__ res,
    const float* __restrict__ gw, const float* __restrict__ bw,
    float* __restrict__ out, __nv_bfloat16* __restrict__ outb)
{
    int row = blockIdx.x * 8 + (threadIdx.x >> 5);
    int lane = threadIdx.x & 31;
    size_t base = (size_t)row * D_MODEL;

    float4 a0 = *reinterpret_cast<const float4*>(y + base + lane * 4);
    float4 r0 = *reinterpret_cast<const float4*>(res + base + lane * 4);
    float4 a1 = *reinterpret_cast<const float4*>(y + base + 128 + lane * 4);
    float4 r1 = *reinterpret_cast<const float4*>(res + base + 128 + lane * 4);
    a0.x += r0.x; a0.y += r0.y; a0.z += r0.z; a0.w += r0.w;
    a1.x += r1.x; a1.y += r1.y; a1.z += r1.z; a1.w += r1.w;

    float s  = a0.x + a0.y + a0.z + a0.w + a1.x + a1.y + a1.z + a1.w;
    float sq = a0.x*a0.x + a0.y*a0.y + a0.z*a0.z + a0.w*a0.w
             + a1.x*a1.x + a1.y*a1.y + a1.z*a1.z + a1.w*a1.w;
#pragma unroll
    for (int o = 16; o; o >>= 1) {
        s  += __shfl_xor_sync(0xffffffffu, s, o);
        sq += __shfl_xor_sync(0xffffffffu, sq, o);
    }
    float mu  = s * (1.f / D_MODEL);
    float var = sq * (1.f / D_MODEL) - mu * mu;
    float inv = rsqrtf(var + LN_EPS);

    float4 g0 = *reinterpret_cast<const float4*>(gw + lane * 4);
    float4 b0 = *reinterpret_cast<const float4*>(bw + lane * 4);
    float4 g1 = *reinterpret_cast<const float4*>(gw + 128 + lane * 4);
    float4 b1 = *reinterpret_cast<const float4*>(bw + 128 + lane * 4);
    float4 o0, o1;
    o0.x = (a0.x - mu) * inv * g0.x + b0.x;
    o0.y = (a0.y - mu) * inv * g0.y + b0.y;
    o0.z = (a0.z - mu) * inv * g0.z + b0.z;
    o0.w = (a0.w - mu) * inv * g0.w + b0.w;
    o1.x = (a1.x - mu) * inv * g1.x + b1.x;
    o1.y = (a1.y - mu) * inv * g1.y + b1.y;
    o1.z = (a1.z - mu) * inv * g1.z + b1.z;
    o1.w = (a1.w - mu) * inv * g1.w + b1.w;
    *reinterpret_cast<float4*>(out + base + lane * 4)       = o0;
    *reinterpret_cast<float4*>(out + base + 128 + lane * 4) = o1;
    if (DUAL) {
        reinterpret_cast<__nv_bfloat162*>(outb + base + lane * 4)[0] = __floats2bfloat162_rn(o0.x, o0.y);
        reinterpret_cast<__nv_bfloat162*>(outb + base + lane * 4)[1] = __floats2bfloat162_rn(o0.z, o0.w);
        reinterpret_cast<__nv_bfloat162*>(outb + base + 128 + lane * 4)[0] = __floats2bfloat162_rn(o1.x, o1.y);
        reinterpret_cast<__nv_bfloat162*>(outb + base + 128 + lane * 4)[1] = __floats2bfloat162_rn(o1.z, o1.w);
    }
}

// ---------------- launch ---------------------------------------------------------
extern "C" void kernel_launch(void* const* d_in, const int* in_sizes, int n_in,
                              void* d_out, int out_size)
{
    const float* x      = (const float*)d_in[0];
    const int*   doc    = (const int*)  d_in[1];
    const float* qkv_w  = (const float*)d_in[2];
    const float* qkv_b  = (const float*)d_in[3];
    const float* out_w  = (const float*)d_in[4];
    const float* out_b  = (const float*)d_in[5];
    const float* ff_w1  = (const float*)d_in[6];
    const float* ff_b1  = (const float*)d_in[7];
    const float* ff_w2  = (const float*)d_in[8];
    const float* ff_b2  = (const float*)d_in[9];
    const float* ln1_g  = (const float*)d_in[10];
    const float* ln1_b  = (const float*)d_in[11];
    const float* ln2_g  = (const float*)d_in[12];
    const float* ln2_b  = (const float*)d_in[13];
    float* out = (float*)d_out;

    float *qkv, *x1, *tmp;
    __nv_bfloat16 *xb, *attnb, *x1b, *ffhb, *wq, *wo, *w1, *w2;
    cudaGetSymbolAddress((void**)&qkv,   g_qkv);
    cudaGetSymbolAddress((void**)&x1,    g_x1);
    cudaGetSymbolAddress((void**)&tmp,   g_tmp);
    cudaGetSymbolAddress((void**)&xb,    g_xb);
    cudaGetSymbolAddress((void**)&attnb, g_attnb);
    cudaGetSymbolAddress((void**)&x1b,   g_x1b);
    cudaGetSymbolAddress((void**)&ffhb,  g_ffhb);
    cudaGetSymbolAddress((void**)&wq,    g_wq);
    cudaGetSymbolAddress((void**)&wo,    g_wo);
    cudaGetSymbolAddress((void**)&w1,    g_w1);
    cudaGetSymbolAddress((void**)&w2,    g_w2);

    // opt-in to >48KB dynamic smem (idempotent host-side attribute sets)
    constexpr int SMBIG = GemmCfg<128, 128>::SMEM;   // 107520
    constexpr int SMSML = GemmCfg<64, 64>::SMEM;     // 55296
    cudaFuncSetAttribute((const void*)gemm_bf16_k<D_MODEL, 3 * D_MODEL, 128, 128, false, false>,
                         cudaFuncAttributeMaxDynamicSharedMemorySize, SMBIG);
    cudaFuncSetAttribute((const void*)gemm_bf16_k<D_MODEL, D_FF, 128, 128, true, true>,
                         cudaFuncAttributeMaxDynamicSharedMemorySize, SMBIG);
    cudaFuncSetAttribute((const void*)gemm_bf16_k<D_MODEL, D_MODEL, 64, 64, false, false>,
                         cudaFuncAttributeMaxDynamicSharedMemorySize, SMSML);
    cudaFuncSetAttribute((const void*)gemm_bf16_k<D_FF, D_MODEL, 64, 64, false, false>,
                         cudaFuncAttributeMaxDynamicSharedMemorySize, SMSML);

    cvt_kernel<<<Q_W2 / 256, 256>>>(x, qkv_w, out_w, ff_w1, ff_w2, xb, wq, wo, w1, w2);
    // QKV: N=768, 128x128 -> grid 6x48
    gemm_bf16_k<D_MODEL, 3 * D_MODEL, 128, 128, false, false><<<dim3(6, 48), 256, SMBIG>>>(xb, wq, qkv_b, qkv);
    attn_kernel<<<(N_TOK * N_HEADS) / 8, 256>>>(qkv, doc, attnb);
    // out-proj: N=256, 64x64 -> grid 4x96=384
    gemm_bf16_k<D_MODEL, D_MODEL, 64, 64, false, false><<<dim3(4, 96), 256, SMSML>>>(attnb, wo, out_b, tmp);
    ln_kernel<true><<<N_TOK / 8, 256>>>(tmp, x, ln1_g, ln1_b, x1, x1b);
    // FF1: N=1024, 128x128 -> grid 8x48
    gemm_bf16_k<D_MODEL, D_FF, 128, 128, true, true><<<dim3(8, 48), 256, SMBIG>>>(x1b, w1, ff_b1, ffhb);
    // FF2: N=256, 64x64 -> grid 4x96=384
    gemm_bf16_k<D_FF, D_MODEL, 64, 64, false, false><<<dim3(4, 96), 256, SMSML>>>(ffhb, w2, ff_b2, tmp);
    ln_kernel<false><<<N_TOK / 8, 256>>>(tmp, x1, ln2_g, ln2_b, out, nullptr);
}